// round 3
// baseline (speedup 1.0000x reference)
#include <cuda_runtime.h>
#include <math.h>

#define NB   128
#define NS   2048
#define DIN  512
#define DM   2048
#define NM   25
#define NH   8
#define NT   10
#define NREP 2080

// ---------------- scratch (device globals; no allocation allowed) ------------
__device__ float g_F0[NS*DIN];
__device__ float g_F1[NS*DIN];
__device__ float g_tmp[NS*DIN];
__device__ float g_KT[2*DIN*NS];          // [tok][n=h*64+d][s]
__device__ float g_Vc[NH*2*NS*64];        // [h][tok][s][d]
__device__ int   g_iu[NREP], g_ju[NREP];
__device__ float g_act[NB*DM];
__device__ float g_alpha_a[NB*NREP];
__device__ float g_alpha_o[NB*NREP];
__device__ float g_s[NB*NREP];
__device__ float g_q[NB*DIN];
__device__ float g_D[2*NH*NB*NS];         // [tok][h][b][s]
__device__ float g_attn[NB*NH*2*NS];      // [b][h][tok][s]
__device__ float g_o1[NB*DIN];
__device__ float g_o2[NB*DIN];
__device__ float g_cat[NB*(DIN+DM)];
__device__ float g_pre[NB*2*DM];
__device__ float g_state[NB*DM];
__device__ float g_ring[NB*DM*NM];
__device__ float g_pred[NB*2*NS];

// ---------------- block reduction ----------------
__device__ __forceinline__ float blockReduce(float v, float* red, bool domax){
    int tid = threadIdx.x;
    #pragma unroll
    for (int o=16;o>0;o>>=1){
        float t = __shfl_xor_sync(0xffffffffu, v, o);
        v = domax ? fmaxf(v,t) : (v+t);
    }
    if ((tid&31)==0) red[tid>>5] = v;
    __syncthreads();
    if (tid < 32){
        float x = (tid < 8) ? red[tid] : (domax ? -3.4e38f : 0.f);
        #pragma unroll
        for (int o=4;o>0;o>>=1){
            float t = __shfl_xor_sync(0xffffffffu, x, o);
            x = domax ? fmaxf(x,t) : (x+t);
        }
        if (tid==0) red[0]=x;
    }
    __syncthreads();
    float out = red[0];
    __syncthreads();
    return out;
}

// ---------------- generic fp32 GEMM ----------------
// C[m,n] (+)= A[m,k] * B[k,n]; BM=BN=64, BK=16, 256 threads, 4x4 per thread.
// grid.x = mTiles*nTiles, grid.y = K-splits (Kchunk each), grid.z = batch.
__global__ void __launch_bounds__(256)
gemm_f32(const float* __restrict__ A, const float* __restrict__ B,
         const float* __restrict__ bias, float* __restrict__ C,
         int Kchunk, int lda, int ldb, int ldc,
         long sA, long sB, long sC, int nTiles, int atomic)
{
    A += (long)blockIdx.z * sA;
    B += (long)blockIdx.z * sB;
    C += (long)blockIdx.z * sC;
    int mt = blockIdx.x / nTiles;
    int nt = blockIdx.x - mt*nTiles;
    int m0 = mt*64, n0 = nt*64;
    int k0 = blockIdx.y * Kchunk;

    __shared__ float As[16][68];
    __shared__ float Bs[16][64];
    int tid = threadIdx.x;
    int tx = tid & 15, ty = tid >> 4;
    int aRow = tid >> 2, aCol = (tid & 3) * 4;
    int bRow = tid >> 4, bCol = (tid & 15) * 4;
    const float* Ap = A + (long)(m0 + aRow)*lda + k0 + aCol;
    const float* Bp = B + (long)(k0 + bRow)*ldb + n0 + bCol;

    float acc[4][4] = {{0.f}};
    for (int kk=0; kk<Kchunk; kk+=16){
        float4 a  = *(const float4*)(Ap + kk);
        float4 b4 = *(const float4*)(Bp + (long)kk*ldb);
        __syncthreads();
        As[aCol+0][aRow]=a.x; As[aCol+1][aRow]=a.y;
        As[aCol+2][aRow]=a.z; As[aCol+3][aRow]=a.w;
        *(float4*)&Bs[bRow][bCol] = b4;
        __syncthreads();
        #pragma unroll
        for (int k=0;k<16;k++){
            float4 av = *(const float4*)&As[k][ty*4];
            float4 bv = *(const float4*)&Bs[k][tx*4];
            acc[0][0]=fmaf(av.x,bv.x,acc[0][0]); acc[0][1]=fmaf(av.x,bv.y,acc[0][1]);
            acc[0][2]=fmaf(av.x,bv.z,acc[0][2]); acc[0][3]=fmaf(av.x,bv.w,acc[0][3]);
            acc[1][0]=fmaf(av.y,bv.x,acc[1][0]); acc[1][1]=fmaf(av.y,bv.y,acc[1][1]);
            acc[1][2]=fmaf(av.y,bv.z,acc[1][2]); acc[1][3]=fmaf(av.y,bv.w,acc[1][3]);
            acc[2][0]=fmaf(av.z,bv.x,acc[2][0]); acc[2][1]=fmaf(av.z,bv.y,acc[2][1]);
            acc[2][2]=fmaf(av.z,bv.z,acc[2][2]); acc[2][3]=fmaf(av.z,bv.w,acc[2][3]);
            acc[3][0]=fmaf(av.w,bv.x,acc[3][0]); acc[3][1]=fmaf(av.w,bv.y,acc[3][1]);
            acc[3][2]=fmaf(av.w,bv.z,acc[3][2]); acc[3][3]=fmaf(av.w,bv.w,acc[3][3]);
        }
    }
    int row0 = m0 + ty*4;
    int col  = n0 + tx*4;
    if (atomic){
        #pragma unroll
        for (int i=0;i<4;i++)
            #pragma unroll
            for (int j=0;j<4;j++)
                atomicAdd(&C[(long)(row0+i)*ldc + col + j], acc[i][j]);
    } else {
        float4 bv = make_float4(0.f,0.f,0.f,0.f);
        if (bias) bv = *(const float4*)&bias[col];
        #pragma unroll
        for (int i=0;i<4;i++){
            float4 o;
            o.x = acc[i][0]+bv.x; o.y = acc[i][1]+bv.y;
            o.z = acc[i][2]+bv.z; o.w = acc[i][3]+bv.w;
            *(float4*)&C[(long)(row0+i)*ldc + col] = o;
        }
    }
}

// ---------------- small kernels ----------------
__global__ void iuju_init(){
    int i = threadIdx.x;
    if (i < 64){
        int off = i*64 - (i*(i-1))/2;
        for (int j=i;j<64;j++){ g_iu[off+j-i]=i; g_ju[off+j-i]=j; }
    }
}

__global__ void fkern(const float* __restrict__ Wpos, const float* __restrict__ bpos,
                      const float* __restrict__ emb){
    int i = blockIdx.x*256+threadIdx.x;
    if (i >= NS*DIN) return;
    int s = i >> 9, d = i & 511;
    float fr = (float)s / (float)(NS-1);
    float sn, cs; sincospif(fr, &sn, &cs);
    float pe = -sn*Wpos[d] + cs*Wpos[DIN+d] + bpos[d];
    g_F0[i] = emb[d]       + pe;
    g_F1[i] = emb[DIN + d] + pe;
}

// 2048x512 -> 512x2048 transpose (g_tmp -> dst)
__global__ void transp(float* __restrict__ dst){
    __shared__ float tile[32][33];
    int s0 = blockIdx.x*32, n0 = blockIdx.y*32;
    int x = threadIdx.x, y = threadIdx.y;
    #pragma unroll
    for (int r=0;r<32;r+=8) tile[y+r][x] = g_tmp[(s0+y+r)*DIN + n0 + x];
    __syncthreads();
    #pragma unroll
    for (int r=0;r<32;r+=8) dst[(n0+y+r)*NS + s0 + x] = tile[x][y+r];
}

__global__ void reshV(int tok){
    int i = blockIdx.x*256+threadIdx.x;
    if (i >= NS*DIN) return;
    int s = i >> 9, n = i & 511;
    int h = n >> 6, d = n & 63;
    g_Vc[(((h*2 + tok)*NS) + s)*64 + d] = g_tmp[i];
}

__global__ void init_state(const float* __restrict__ sa, const float* __restrict__ st){
    int i = blockIdx.x*256+threadIdx.x;
    if (i < NB*DM) g_act[i] = sa[i & (DM-1)];
    if (i < NB*DM*NM){
        int rem = i % (DM*NM);
        g_ring[i] = st[rem];
    }
}

__global__ void fillb(float* __restrict__ C, const float* __restrict__ bias, int N, int total){
    int i = blockIdx.x*256+threadIdx.x;
    if (i < total) C[i] = bias ? bias[i % N] : 0.f;
}

__global__ void sync_k(const float* __restrict__ decay, float* __restrict__ alpha,
                       int base, int t){
    int b = blockIdx.x;
    __shared__ float sel[64];
    int tid = threadIdx.x;
    if (tid < 64) sel[tid] = g_act[b*DM + base + tid];
    __syncthreads();
    for (int p=tid; p<NREP; p+=256){
        float pair = sel[g_iu[p]] * sel[g_ju[p]];
        float r = expf(-decay[p]);
        float al = (t==0) ? pair : fmaf(r, alpha[b*NREP+p], pair);
        alpha[b*NREP+p] = al;
        float bet = 1.f;
        for (int k=0;k<t;k++) bet = fmaf(r, bet, 1.f);
        g_s[b*NREP+p] = al * rsqrtf(bet);
    }
}

__global__ void __launch_bounds__(256) softmax_sel(const int* __restrict__ tokens){
    int b = blockIdx.x, h = blockIdx.y;
    __shared__ float sv[NS];
    __shared__ unsigned char tks[NS];
    __shared__ float red[8];
    int tid = threadIdx.x;
    float mx = -3.4e38f;
    for (int s=tid;s<NS;s+=256){
        int tk = tokens[b*NS+s];
        float v = g_D[(((tk*NH + h)*NB) + b)*NS + s] * 0.125f;
        sv[s]=v; tks[s]=(unsigned char)tk;
        mx = fmaxf(mx,v);
    }
    mx = blockReduce(mx, red, true);
    float sum=0.f;
    for (int s=tid;s<NS;s+=256){ float e = expf(sv[s]-mx); sv[s]=e; sum+=e; }
    sum = blockReduce(sum, red, false);
    float inv = 1.f/sum;
    long base = ((long)b*NH + h)*2*NS;
    for (int s=tid;s<NS;s+=256){
        int tk = tks[s];
        g_attn[base + tk*NS + s]     = sv[s]*inv;
        g_attn[base + (1-tk)*NS + s] = 0.f;
    }
}

__global__ void concat_k(){
    int i = blockIdx.x*256+threadIdx.x;
    if (i >= NB*(DIN+DM)) return;
    int b = i / (DIN+DM), c = i - b*(DIN+DM);
    g_cat[i] = (c < DIN) ? g_o2[b*DIN + c] : g_act[b*DM + (c - DIN)];
}

__global__ void __launch_bounds__(256) glu_ln(const float* __restrict__ g,
                                              const float* __restrict__ bb){
    int b = blockIdx.x, tid = threadIdx.x;
    __shared__ float v[DM];
    __shared__ float red[8];
    float lsum=0.f;
    for (int n=tid;n<DM;n+=256){
        float g1 = g_pre[b*2*DM + n];
        float g2 = g_pre[b*2*DM + DM + n];
        float x = g1 / (1.f + expf(-g2));
        v[n]=x; lsum+=x;
    }
    float mu = blockReduce(lsum, red, false) * (1.f/DM);
    float lv=0.f;
    for (int n=tid;n<DM;n+=256){ float d0=v[n]-mu; lv = fmaf(d0,d0,lv); }
    float var = blockReduce(lv, red, false) * (1.f/DM);
    float rs = rsqrtf(var + 1e-5f);
    for (int n=tid;n<DM;n+=256)
        g_state[b*DM+n] = (v[n]-mu)*rs*g[n] + bb[n];
}

__global__ void trace_act(const float* __restrict__ lg, const float* __restrict__ lb,
                          const float* __restrict__ Wn, const float* __restrict__ bn,
                          const float* __restrict__ temp, int t){
    int b = blockIdx.x;
    int n = blockIdx.y*256 + threadIdx.x;
    float* ring = &g_ring[((long)b*DM + n)*NM];
    ring[t % NM] = g_state[b*DM + n];
    float vals[NM];
    float mu = 0.f;
    #pragma unroll
    for (int m=0;m<NM;m++){
        int slot = (t+1+m) % NM;
        vals[m] = ring[slot];
        mu += vals[m];
    }
    mu *= (1.f/NM);
    float var = 0.f;
    #pragma unroll
    for (int m=0;m<NM;m++){ float d0 = vals[m]-mu; var = fmaf(d0,d0,var); }
    var *= (1.f/NM);
    float rs = rsqrtf(var + 1e-5f);
    float y0 = bn[n*2+0], y1 = bn[n*2+1];
    #pragma unroll
    for (int m=0;m<NM;m++){
        float xn = (vals[m]-mu)*rs*lg[m] + lb[m];
        y0 = fmaf(xn, Wn[(m*2+0)*DM + n], y0);
        y1 = fmaf(xn, Wn[(m*2+1)*DM + n], y1);
    }
    g_act[b*DM + n] = y0 * (1.f/(1.f + expf(-y1))) / temp[0];
}

__global__ void __launch_bounds__(256) finalize(float* __restrict__ out, int t){
    int b = blockIdx.x, tid = threadIdx.x;
    __shared__ float red[8];
    float sum = 0.f;
    for (int s=tid; s<NS; s+=256){
        float l0 = g_pred[b*4096 + 2*s];
        float l1 = g_pred[b*4096 + 2*s + 1];
        out[((long)b*4096 + 2*s)*NT + t]     = l0;
        out[((long)b*4096 + 2*s + 1)*NT + t] = l1;
        float m = fmaxf(l0,l1);
        float e0 = expf(l0-m), e1 = expf(l1-m);
        float Z = e0+e1;
        float ent = (logf(Z) - (e0*(l0-m) + e1*(l1-m))/Z) * 1.4426950408889634f;
        sum += ent;
    }
    sum = blockReduce(sum, red, false);
    if (tid == 0){
        float ne = sum * (1.f/NS);
        float* certs = out + (long)NB*4096*NT;
        certs[(b*2+0)*NT + t] = ne;
        certs[(b*2+1)*NT + t] = 1.f - ne;
    }
}

// ---------------- host ----------------
extern "C" void kernel_launch(void* const* d_in, const int* in_sizes, int n_in,
                              void* d_out, int out_size) {
    const int*   tokens = (const int*)  d_in[0];
    const float* emb    = (const float*)d_in[1];
    const float* W_pos  = (const float*)d_in[2];
    const float* b_pos  = (const float*)d_in[3];
    const float* Wq     = (const float*)d_in[4];
    const float* bq     = (const float*)d_in[5];
    const float* Wk     = (const float*)d_in[6];
    const float* bk     = (const float*)d_in[7];
    const float* Wv     = (const float*)d_in[8];
    const float* bv     = (const float*)d_in[9];
    const float* Wo     = (const float*)d_in[10];
    const float* bo     = (const float*)d_in[11];
    const float* Ws     = (const float*)d_in[12];
    const float* bs     = (const float*)d_in[13];
    const float* ln_s_g = (const float*)d_in[14];
    const float* ln_s_b = (const float*)d_in[15];
    const float* ln_n_g = (const float*)d_in[16];
    const float* ln_n_b = (const float*)d_in[17];
    const float* Wn     = (const float*)d_in[18];
    const float* bn     = (const float*)d_in[19];
    const float* temp   = (const float*)d_in[20];
    const float* Wout   = (const float*)d_in[21];
    const float* bout   = (const float*)d_in[22];
    const float* s_act  = (const float*)d_in[23];
    const float* s_tr   = (const float*)d_in[24];
    const float* dec_a  = (const float*)d_in[25];
    const float* dec_o  = (const float*)d_in[26];
    float* out = (float*)d_out;

    float *F0,*F1,*tmp,*KT,*Vc,*act,*al_a,*al_o,*sp,*qp,*Dp,*attnp,*o1p,*o2p,*catp,*prep,*predp;
    cudaGetSymbolAddress((void**)&F0,   g_F0);
    cudaGetSymbolAddress((void**)&F1,   g_F1);
    cudaGetSymbolAddress((void**)&tmp,  g_tmp);
    cudaGetSymbolAddress((void**)&KT,   g_KT);
    cudaGetSymbolAddress((void**)&Vc,   g_Vc);
    cudaGetSymbolAddress((void**)&act,  g_act);
    cudaGetSymbolAddress((void**)&al_a, g_alpha_a);
    cudaGetSymbolAddress((void**)&al_o, g_alpha_o);
    cudaGetSymbolAddress((void**)&sp,   g_s);
    cudaGetSymbolAddress((void**)&qp,   g_q);
    cudaGetSymbolAddress((void**)&Dp,   g_D);
    cudaGetSymbolAddress((void**)&attnp,g_attn);
    cudaGetSymbolAddress((void**)&o1p,  g_o1);
    cudaGetSymbolAddress((void**)&o2p,  g_o2);
    cudaGetSymbolAddress((void**)&catp, g_cat);
    cudaGetSymbolAddress((void**)&prep, g_pre);
    cudaGetSymbolAddress((void**)&predp,g_pred);

    // -------- precompute --------
    iuju_init<<<1,64>>>();
    fkern<<<(NS*DIN)/256, 256>>>(W_pos, b_pos, emb);
    // K0, K1 -> transposed [tok][n][s]
    gemm_f32<<<dim3(32*8,1,1),256>>>(F0, Wk, bk, tmp, 512, 512,512,512, 0,0,0, 8, 0);
    transp<<<dim3(64,16),dim3(32,8)>>>(KT);
    gemm_f32<<<dim3(32*8,1,1),256>>>(F1, Wk, bk, tmp, 512, 512,512,512, 0,0,0, 8, 0);
    transp<<<dim3(64,16),dim3(32,8)>>>(KT + (long)DIN*NS);
    // V0, V1 -> [h][tok][s][d]
    gemm_f32<<<dim3(32*8,1,1),256>>>(F0, Wv, bv, tmp, 512, 512,512,512, 0,0,0, 8, 0);
    reshV<<<(NS*DIN)/256,256>>>(0);
    gemm_f32<<<dim3(32*8,1,1),256>>>(F1, Wv, bv, tmp, 512, 512,512,512, 0,0,0, 8, 0);
    reshV<<<(NS*DIN)/256,256>>>(1);
    init_state<<<(NB*DM*NM + 255)/256, 256>>>(s_act, s_tr);

    // -------- T iterations --------
    for (int t=0; t<NT; t++){
        // sync over action neurons (last 64 of act)
        sync_k<<<NB,256>>>(dec_a, al_a, DM-64, t);
        // q = s @ Wq + bq  (split-K 5x416, atomic into bias-prefilled q)
        fillb<<<(NB*DIN)/256,256>>>(qp, bq, DIN, NB*DIN);
        gemm_f32<<<dim3(16,5,1),256>>>(sp, Wq, nullptr, qp, 416, NREP, DIN, DIN, 0,0,0, 8, 1);
        // scores for both token variants: D[tok][h][b][s]
        for (int tok=0; tok<2; tok++){
            gemm_f32<<<dim3(2*32,1,NH),256>>>(
                qp, KT + (long)tok*DIN*NS, nullptr, Dp + (long)tok*NH*NB*NS,
                64, DIN, NS, NS, 64L, 64L*NS, (long)NB*NS, 32, 0);
        }
        softmax_sel<<<dim3(NB,NH),256>>>(tokens);
        // o1[b, h*64+d] = attn[b,h,:] @ Vc[h]   (split-K 8x512, atomic)
        fillb<<<(NB*DIN)/256,256>>>(o1p, nullptr, 1, NB*DIN);
        gemm_f32<<<dim3(2,8,NH),256>>>(attnp, Vc, nullptr, o1p,
                512, NH*2*NS, 64, DIN, 2L*NS, 2L*NS*64, 64L, 1, 1);
        // o2 = o1 @ Wo + bo (split-K 4x128, atomic)
        fillb<<<(NB*DIN)/256,256>>>(o2p, bo, DIN, NB*DIN);
        gemm_f32<<<dim3(16,4,1),256>>>(o1p, Wo, nullptr, o2p, 128, DIN,DIN,DIN, 0,0,0, 8, 1);
        concat_k<<<(NB*(DIN+DM))/256,256>>>();
        // pre = cat @ Ws + bs
        gemm_f32<<<dim3(2*64,1,1),256>>>(catp, Ws, bs, prep, DIN+DM, DIN+DM, 2*DM, 2*DM, 0,0,0, 64, 0);
        glu_ln<<<NB,256>>>(ln_s_g, ln_s_b);
        trace_act<<<dim3(NB,DM/256),256>>>(ln_n_g, ln_n_b, Wn, bn, temp, t);
        // sync over output neurons (first 64 of act)
        sync_k<<<NB,256>>>(dec_o, al_o, 0, t);
        // pred = s @ Wout + bout
        gemm_f32<<<dim3(2*64,1,1),256>>>(sp, Wout, bout, predp, NREP, NREP, 2*NS, 2*NS, 0,0,0, 64, 0);
        finalize<<<NB,256>>>(out, t);
    }
}

// round 4
// speedup vs baseline: 1.1533x; 1.1533x over previous
#include <cuda_runtime.h>
#include <math.h>

#define NB   128
#define NS   2048
#define DIN  512
#define DM   2048
#define NM   25
#define NH   8
#define NT   10
#define NREP 2080

typedef unsigned long long ull;

// ---------------- scratch (device globals; no allocation allowed) ------------
__device__ float g_F0[NS*DIN];
__device__ float g_F1[NS*DIN];
__device__ float g_tmp[NS*DIN];
__device__ float g_KT[2*DIN*NS];          // [tok][n=h*64+d][s]
__device__ float g_Vc[NH*2*NS*64];        // [h][tok][s][d]
__device__ int   g_iu[NREP], g_ju[NREP];
__device__ float g_act[NB*DM];
__device__ float g_alpha_a[NB*NREP];
__device__ float g_alpha_o[NB*NREP];
__device__ float g_s[NB*NREP];
__device__ float g_q[NB*DIN];
__device__ float g_D[2*NH*NB*NS];         // [tok][h][b][s]
__device__ float g_attn[NB*NH*2*NS];      // [b][h][tok][s]
__device__ float g_o1[NB*DIN];
__device__ float g_o2[NB*DIN];
__device__ float g_cat[NB*(DIN+DM)];
__device__ float g_pre[NB*2*DM];
__device__ float g_state[NB*DM];
__device__ float g_ring[NB*DM*NM];
__device__ float g_pred[NB*2*NS];

// ---------------- helpers ----------------
__device__ __forceinline__ ull dup2(float x){
    ull r; unsigned u = __float_as_uint(x);
    asm("mov.b64 %0, {%1, %1};" : "=l"(r) : "r"(u));
    return r;
}
#define FMA2(d,a,b) asm("fma.rn.f32x2 %0, %1, %2, %3;" : "=l"(d) : "l"(a), "l"(b), "l"(d))

__device__ __forceinline__ float blockReduce(float v, float* red, bool domax){
    int tid = threadIdx.x;
    #pragma unroll
    for (int o=16;o>0;o>>=1){
        float t = __shfl_xor_sync(0xffffffffu, v, o);
        v = domax ? fmaxf(v,t) : (v+t);
    }
    if ((tid&31)==0) red[tid>>5] = v;
    __syncthreads();
    if (tid < 32){
        float x = (tid < 8) ? red[tid] : (domax ? -3.4e38f : 0.f);
        #pragma unroll
        for (int o=4;o>0;o>>=1){
            float t = __shfl_xor_sync(0xffffffffu, x, o);
            x = domax ? fmaxf(x,t) : (x+t);
        }
        if (tid==0) red[0]=x;
    }
    __syncthreads();
    float out = red[0];
    __syncthreads();
    return out;
}

// ---------------- fp32x2 GEMM ----------------
// C[m,n] (+)= A[m,k]*B[k,n].  BM=128 fixed, BK=8, 256 threads.
// BN=128 -> 8x8 per thread; BN=64 -> 8x4 per thread.
// grid.x = mTiles*nTiles, grid.y = K-splits (Kchunk each), grid.z = batch.
template<int BN, int TN>
__global__ void __launch_bounds__(256)
gemm_t(const float* __restrict__ A, const float* __restrict__ B,
       const float* __restrict__ bias, float* __restrict__ C,
       int Kchunk, int lda, int ldb, int ldc,
       long sA, long sB, long sC, int nTiles, int atomic)
{
    A += (long)blockIdx.z * sA;
    B += (long)blockIdx.z * sB;
    C += (long)blockIdx.z * sC;
    int mt = blockIdx.x / nTiles;
    int nt = blockIdx.x - mt*nTiles;
    int m0 = mt*128, n0 = nt*BN;
    int k0 = blockIdx.y * Kchunk;

    __shared__ float As[8][132];
    __shared__ float Bs[8][BN];
    int tid = threadIdx.x;
    const int NCOL = BN / TN;             // threads along n
    int tx = tid % NCOL, ty = tid / NCOL; // ty in [0, 256/NCOL)

    // A tile load: 128x8 floats, float4 per thread
    int aRow = tid >> 1, aCol = (tid & 1)*4;
    const float* Ap = A + (long)(m0 + aRow)*lda + k0 + aCol;
    // B tile load
    int bRow, bCol;
    if (BN == 128){ bRow = tid >> 5; bCol = (tid & 31)*4; }
    else          { bRow = tid >> 5; bCol = (tid & 31)*2; }
    const float* Bp = B + (long)(k0 + bRow)*ldb + n0 + bCol;

    ull acc[8][TN/2];
    #pragma unroll
    for (int i=0;i<8;i++)
        #pragma unroll
        for (int j=0;j<TN/2;j++) acc[i][j] = 0ull;

    for (int kk=0; kk<Kchunk; kk+=8){
        float4 a = *(const float4*)(Ap + kk);
        float4 b4; float2 b2;
        if (BN == 128) b4 = *(const float4*)(Bp + (long)kk*ldb);
        else           b2 = *(const float2*)(Bp + (long)kk*ldb);
        __syncthreads();
        As[aCol+0][aRow]=a.x; As[aCol+1][aRow]=a.y;
        As[aCol+2][aRow]=a.z; As[aCol+3][aRow]=a.w;
        if (BN == 128) *(float4*)&Bs[bRow][bCol] = b4;
        else           *(float2*)&Bs[bRow][bCol] = b2;
        __syncthreads();
        #pragma unroll
        for (int k=0;k<8;k++){
            float4 a0 = *(const float4*)&As[k][ty*8];
            float4 a1 = *(const float4*)&As[k][ty*8+4];
            float am[8] = {a0.x,a0.y,a0.z,a0.w,a1.x,a1.y,a1.z,a1.w};
            ull bp[TN/2];
            #pragma unroll
            for (int j=0;j<TN/2;j++)
                bp[j] = *(const ull*)&Bs[k][tx*TN + 2*j];
            #pragma unroll
            for (int i=0;i<8;i++){
                ull ad = dup2(am[i]);
                #pragma unroll
                for (int j=0;j<TN/2;j++)
                    FMA2(acc[i][j], ad, bp[j]);
            }
        }
    }
    int row0 = m0 + ty*8;
    int col  = n0 + tx*TN;
    if (atomic){
        #pragma unroll
        for (int i=0;i<8;i++)
            #pragma unroll
            for (int j=0;j<TN/2;j++){
                float2 v = *(float2*)&acc[i][j];
                atomicAdd(&C[(long)(row0+i)*ldc + col + 2*j],     v.x);
                atomicAdd(&C[(long)(row0+i)*ldc + col + 2*j + 1], v.y);
            }
    } else {
        float bvv[TN];
        #pragma unroll
        for (int j=0;j<TN;j++) bvv[j] = bias ? bias[col+j] : 0.f;
        #pragma unroll
        for (int i=0;i<8;i++){
            float o[TN];
            #pragma unroll
            for (int j=0;j<TN/2;j++){
                float2 v = *(float2*)&acc[i][j];
                o[2*j] = v.x + bvv[2*j]; o[2*j+1] = v.y + bvv[2*j+1];
            }
            #pragma unroll
            for (int j=0;j<TN;j+=4)
                *(float4*)&C[(long)(row0+i)*ldc + col + j] = *(float4*)&o[j];
        }
    }
}

// ---------------- small kernels ----------------
__global__ void iuju_init(){
    int i = threadIdx.x;
    if (i < 64){
        int off = i*64 - (i*(i-1))/2;
        for (int j=i;j<64;j++){ g_iu[off+j-i]=i; g_ju[off+j-i]=j; }
    }
}

__global__ void fkern(const float* __restrict__ Wpos, const float* __restrict__ bpos,
                      const float* __restrict__ emb){
    int i = blockIdx.x*256+threadIdx.x;
    if (i >= NS*DIN) return;
    int s = i >> 9, d = i & 511;
    float fr = (float)s / (float)(NS-1);
    float sn, cs; sincospif(fr, &sn, &cs);
    float pe = -sn*Wpos[d] + cs*Wpos[DIN+d] + bpos[d];
    g_F0[i] = emb[d]       + pe;
    g_F1[i] = emb[DIN + d] + pe;
}

__global__ void transp(float* __restrict__ dst){
    __shared__ float tile[32][33];
    int s0 = blockIdx.x*32, n0 = blockIdx.y*32;
    int x = threadIdx.x, y = threadIdx.y;
    #pragma unroll
    for (int r=0;r<32;r+=8) tile[y+r][x] = g_tmp[(s0+y+r)*DIN + n0 + x];
    __syncthreads();
    #pragma unroll
    for (int r=0;r<32;r+=8) dst[(n0+y+r)*NS + s0 + x] = tile[x][y+r];
}

__global__ void reshV(int tok){
    int i = blockIdx.x*256+threadIdx.x;
    if (i >= NS*DIN) return;
    int s = i >> 9, n = i & 511;
    int h = n >> 6, d = n & 63;
    g_Vc[(((h*2 + tok)*NS) + s)*64 + d] = g_tmp[i];
}

__global__ void init_state(const float* __restrict__ sa, const float* __restrict__ st){
    int i = blockIdx.x*256+threadIdx.x;
    if (i < NB*DM) g_act[i] = sa[i & (DM-1)];
    if (i < NB*DM*NM){
        int rem = i % (DM*NM);
        g_ring[i] = st[rem];
    }
}

__global__ void fillb(float* __restrict__ C, const float* __restrict__ bias, int N, int total){
    int i = blockIdx.x*256+threadIdx.x;
    if (i < total) C[i] = bias ? bias[i % N] : 0.f;
}

__global__ void sync_k(const float* __restrict__ decay, float* __restrict__ alpha,
                       int base, int t){
    int b = blockIdx.x;
    __shared__ float sel[64];
    int tid = threadIdx.x;
    if (tid < 64) sel[tid] = g_act[b*DM + base + tid];
    __syncthreads();
    for (int p=tid; p<NREP; p+=256){
        float pair = sel[g_iu[p]] * sel[g_ju[p]];
        float r = expf(-decay[p]);
        float al = (t==0) ? pair : fmaf(r, alpha[b*NREP+p], pair);
        alpha[b*NREP+p] = al;
        float bet = 1.f;
        for (int k=0;k<t;k++) bet = fmaf(r, bet, 1.f);
        g_s[b*NREP+p] = al * rsqrtf(bet);
    }
}

__global__ void __launch_bounds__(256) softmax_sel(const int* __restrict__ tokens){
    int b = blockIdx.x, h = blockIdx.y;
    __shared__ float sv[NS];
    __shared__ unsigned char tks[NS];
    __shared__ float red[8];
    int tid = threadIdx.x;
    float mx = -3.4e38f;
    for (int s=tid;s<NS;s+=256){
        int tk = tokens[b*NS+s];
        float v = g_D[(((tk*NH + h)*NB) + b)*NS + s] * 0.125f;
        sv[s]=v; tks[s]=(unsigned char)tk;
        mx = fmaxf(mx,v);
    }
    mx = blockReduce(mx, red, true);
    float sum=0.f;
    for (int s=tid;s<NS;s+=256){ float e = expf(sv[s]-mx); sv[s]=e; sum+=e; }
    sum = blockReduce(sum, red, false);
    float inv = 1.f/sum;
    long base = ((long)b*NH + h)*2*NS;
    for (int s=tid;s<NS;s+=256){
        int tk = tks[s];
        g_attn[base + tk*NS + s]     = sv[s]*inv;
        g_attn[base + (1-tk)*NS + s] = 0.f;
    }
}

__global__ void concat_k(){
    int i = blockIdx.x*256+threadIdx.x;
    if (i >= NB*(DIN+DM)) return;
    int b = i / (DIN+DM), c = i - b*(DIN+DM);
    g_cat[i] = (c < DIN) ? g_o2[b*DIN + c] : g_act[b*DM + (c - DIN)];
}

__global__ void __launch_bounds__(256) glu_ln(const float* __restrict__ g,
                                              const float* __restrict__ bb){
    int b = blockIdx.x, tid = threadIdx.x;
    __shared__ float v[DM];
    __shared__ float red[8];
    float lsum=0.f;
    for (int n=tid;n<DM;n+=256){
        float g1 = g_pre[b*2*DM + n];
        float g2 = g_pre[b*2*DM + DM + n];
        float x = g1 / (1.f + expf(-g2));
        v[n]=x; lsum+=x;
    }
    float mu = blockReduce(lsum, red, false) * (1.f/DM);
    float lv=0.f;
    for (int n=tid;n<DM;n+=256){ float d0=v[n]-mu; lv = fmaf(d0,d0,lv); }
    float var = blockReduce(lv, red, false) * (1.f/DM);
    float rs = rsqrtf(var + 1e-5f);
    for (int n=tid;n<DM;n+=256)
        g_state[b*DM+n] = (v[n]-mu)*rs*g[n] + bb[n];
}

__global__ void trace_act(const float* __restrict__ lg, const float* __restrict__ lb,
                          const float* __restrict__ Wn, const float* __restrict__ bn,
                          const float* __restrict__ temp, int t){
    int b = blockIdx.x;
    int n = blockIdx.y*256 + threadIdx.x;
    float* ring = &g_ring[((long)b*DM + n)*NM];
    ring[t % NM] = g_state[b*DM + n];
    float vals[NM];
    float mu = 0.f;
    #pragma unroll
    for (int m=0;m<NM;m++){
        int slot = (t+1+m) % NM;
        vals[m] = ring[slot];
        mu += vals[m];
    }
    mu *= (1.f/NM);
    float var = 0.f;
    #pragma unroll
    for (int m=0;m<NM;m++){ float d0 = vals[m]-mu; var = fmaf(d0,d0,var); }
    var *= (1.f/NM);
    float rs = rsqrtf(var + 1e-5f);
    float y0 = bn[n*2+0], y1 = bn[n*2+1];
    #pragma unroll
    for (int m=0;m<NM;m++){
        float xn = (vals[m]-mu)*rs*lg[m] + lb[m];
        y0 = fmaf(xn, Wn[(m*2+0)*DM + n], y0);
        y1 = fmaf(xn, Wn[(m*2+1)*DM + n], y1);
    }
    g_act[b*DM + n] = y0 * (1.f/(1.f + expf(-y1))) / temp[0];
}

__global__ void __launch_bounds__(256) finalize(float* __restrict__ out, int t){
    int b = blockIdx.x, tid = threadIdx.x;
    __shared__ float red[8];
    float sum = 0.f;
    for (int s=tid; s<NS; s+=256){
        float l0 = g_pred[b*4096 + 2*s];
        float l1 = g_pred[b*4096 + 2*s + 1];
        out[((long)b*4096 + 2*s)*NT + t]     = l0;
        out[((long)b*4096 + 2*s + 1)*NT + t] = l1;
        float m = fmaxf(l0,l1);
        float e0 = expf(l0-m), e1 = expf(l1-m);
        float Z = e0+e1;
        float ent = (logf(Z) - (e0*(l0-m) + e1*(l1-m))/Z) * 1.4426950408889634f;
        sum += ent;
    }
    sum = blockReduce(sum, red, false);
    if (tid == 0){
        float ne = sum * (1.f/NS);
        float* certs = out + (long)NB*4096*NT;
        certs[(b*2+0)*NT + t] = ne;
        certs[(b*2+1)*NT + t] = 1.f - ne;
    }
}

// ---------------- host ----------------
extern "C" void kernel_launch(void* const* d_in, const int* in_sizes, int n_in,
                              void* d_out, int out_size) {
    const int*   tokens = (const int*)  d_in[0];
    const float* emb    = (const float*)d_in[1];
    const float* W_pos  = (const float*)d_in[2];
    const float* b_pos  = (const float*)d_in[3];
    const float* Wq     = (const float*)d_in[4];
    const float* bq     = (const float*)d_in[5];
    const float* Wk     = (const float*)d_in[6];
    const float* bk     = (const float*)d_in[7];
    const float* Wv     = (const float*)d_in[8];
    const float* bv     = (const float*)d_in[9];
    const float* Wo     = (const float*)d_in[10];
    const float* bo     = (const float*)d_in[11];
    const float* Ws     = (const float*)d_in[12];
    const float* bs     = (const float*)d_in[13];
    const float* ln_s_g = (const float*)d_in[14];
    const float* ln_s_b = (const float*)d_in[15];
    const float* ln_n_g = (const float*)d_in[16];
    const float* ln_n_b = (const float*)d_in[17];
    const float* Wn     = (const float*)d_in[18];
    const float* bn     = (const float*)d_in[19];
    const float* temp   = (const float*)d_in[20];
    const float* Wout   = (const float*)d_in[21];
    const float* bout   = (const float*)d_in[22];
    const float* s_act  = (const float*)d_in[23];
    const float* s_tr   = (const float*)d_in[24];
    const float* dec_a  = (const float*)d_in[25];
    const float* dec_o  = (const float*)d_in[26];
    float* out = (float*)d_out;

    float *F0,*F1,*tmp,*KT,*Vc,*al_a,*al_o,*sp,*qp,*Dp,*attnp,*o1p,*o2p,*catp,*prep,*predp;
    cudaGetSymbolAddress((void**)&F0,   g_F0);
    cudaGetSymbolAddress((void**)&F1,   g_F1);
    cudaGetSymbolAddress((void**)&tmp,  g_tmp);
    cudaGetSymbolAddress((void**)&KT,   g_KT);
    cudaGetSymbolAddress((void**)&Vc,   g_Vc);
    cudaGetSymbolAddress((void**)&al_a, g_alpha_a);
    cudaGetSymbolAddress((void**)&al_o, g_alpha_o);
    cudaGetSymbolAddress((void**)&sp,   g_s);
    cudaGetSymbolAddress((void**)&qp,   g_q);
    cudaGetSymbolAddress((void**)&Dp,   g_D);
    cudaGetSymbolAddress((void**)&attnp,g_attn);
    cudaGetSymbolAddress((void**)&o1p,  g_o1);
    cudaGetSymbolAddress((void**)&o2p,  g_o2);
    cudaGetSymbolAddress((void**)&catp, g_cat);
    cudaGetSymbolAddress((void**)&prep, g_pre);
    cudaGetSymbolAddress((void**)&predp,g_pred);

    // -------- precompute --------
    iuju_init<<<1,64>>>();
    fkern<<<(NS*DIN)/256, 256>>>(W_pos, b_pos, emb);
    // K0, K1 -> transposed [tok][n][s]   (M=2048, N=512, K=512)
    gemm_t<128,8><<<dim3(16*4,1,1),256>>>(F0, Wk, bk, tmp, 512, 512,512,512, 0,0,0, 4, 0);
    transp<<<dim3(64,16),dim3(32,8)>>>(KT);
    gemm_t<128,8><<<dim3(16*4,1,1),256>>>(F1, Wk, bk, tmp, 512, 512,512,512, 0,0,0, 4, 0);
    transp<<<dim3(64,16),dim3(32,8)>>>(KT + (long)DIN*NS);
    // V0, V1 -> [h][tok][s][d]
    gemm_t<128,8><<<dim3(16*4,1,1),256>>>(F0, Wv, bv, tmp, 512, 512,512,512, 0,0,0, 4, 0);
    reshV<<<(NS*DIN)/256,256>>>(0);
    gemm_t<128,8><<<dim3(16*4,1,1),256>>>(F1, Wv, bv, tmp, 512, 512,512,512, 0,0,0, 4, 0);
    reshV<<<(NS*DIN)/256,256>>>(1);
    init_state<<<(NB*DM*NM + 255)/256, 256>>>(s_act, s_tr);

    // -------- T iterations --------
    for (int t=0; t<NT; t++){
        // sync over action neurons (last 64 of act)
        sync_k<<<NB,256>>>(dec_a, al_a, DM-64, t);
        // q = s @ Wq + bq : M=128, N=512, K=2080 -> BN=64, 8 ntiles x 13 splits
        fillb<<<(NB*DIN)/256,256>>>(qp, bq, DIN, NB*DIN);
        gemm_t<64,4><<<dim3(8,13,1),256>>>(sp, Wq, nullptr, qp, 160, NREP, DIN, DIN, 0,0,0, 8, 1);
        // scores: per (tok, h): M=128, N=2048, K=64
        for (int tok=0; tok<2; tok++){
            gemm_t<128,8><<<dim3(16,1,NH),256>>>(
                qp, KT + (long)tok*DIN*NS, nullptr, Dp + (long)tok*NH*NB*NS,
                64, DIN, NS, NS, 64L, 64L*NS, (long)NB*NS, 16, 0);
        }
        softmax_sel<<<dim3(NB,NH),256>>>(tokens);
        // o1: per h: M=128, N=64, K=4096 -> BN=64, 16 splits
        fillb<<<(NB*DIN)/256,256>>>(o1p, nullptr, 1, NB*DIN);
        gemm_t<64,4><<<dim3(1,16,NH),256>>>(attnp, Vc, nullptr, o1p,
                256, NH*2*NS, 64, DIN, 2L*NS, 2L*NS*64, 64L, 1, 1);
        // o2 = o1 @ Wo + bo : M=128, N=512, K=512 -> BN=64, 8 ntiles x 4 splits
        fillb<<<(NB*DIN)/256,256>>>(o2p, bo, DIN, NB*DIN);
        gemm_t<64,4><<<dim3(8,4,1),256>>>(o1p, Wo, nullptr, o2p, 128, DIN,DIN,DIN, 0,0,0, 8, 1);
        concat_k<<<(NB*(DIN+DM))/256,256>>>();
        // pre = cat @ Ws + bs : M=128, N=4096, K=2560 -> 32 ntiles x 4 splits
        fillb<<<(NB*2*DM)/256,256>>>(prep, bs, 2*DM, NB*2*DM);
        gemm_t<128,8><<<dim3(32,4,1),256>>>(catp, Ws, nullptr, prep, 640, DIN+DM, 2*DM, 2*DM, 0,0,0, 32, 1);
        glu_ln<<<NB,256>>>(ln_s_g, ln_s_b);
        trace_act<<<dim3(NB,DM/256),256>>>(ln_n_g, ln_n_b, Wn, bn, temp, t);
        // sync over output neurons (first 64 of act)
        sync_k<<<NB,256>>>(dec_o, al_o, 0, t);
        // pred = s @ Wout + bout : M=128, N=4096, K=2080 -> 32 ntiles x 4 splits
        fillb<<<(NB*2*NS)/256,256>>>(predp, bout, 2*NS, NB*2*NS);
        gemm_t<128,8><<<dim3(32,4,1),256>>>(sp, Wout, nullptr, predp, 520, NREP, 2*NS, 2*NS, 0,0,0, 32, 1);
        finalize<<<NB,256>>>(out, t);
    }
}

// round 5
// speedup vs baseline: 1.7464x; 1.5143x over previous
#include <cuda_runtime.h>
#include <math.h>

#define NB   128
#define NS   2048
#define DIN  512
#define DM   2048
#define NM   25
#define NH   8
#define NT   10
#define NREP 2080

typedef unsigned long long ull;

// ---------------- scratch (device globals; no allocation allowed) ------------
__device__ float g_F[2*NS*DIN];
__device__ float g_tmp[2*NS*DIN];
__device__ float g_KT[2*DIN*NS];          // [tok][n=h*64+d][s]
__device__ float g_Vc[NH*2*NS*64];        // [h][tok][s][d]
__device__ int   g_iu[NREP], g_ju[NREP];
__device__ float g_act[NB*DM];
__device__ float g_alpha_a[NB*NREP];
__device__ float g_alpha_o[NB*NREP];
__device__ float g_s[NB*NREP];
__device__ float g_q[NB*DIN];
__device__ float g_D[2*NH*NB*NS];         // [tok][h][b][s]
__device__ float g_attn[NB*NH*2*NS];      // [b][h][tok][s]
__device__ float g_o1[NB*DIN];
__device__ float g_o2[NB*DIN];
__device__ float g_cat[NB*(DIN+DM)];
__device__ float g_pre[NB*2*DM];
__device__ float g_state[NB*DM];
__device__ float g_ring[NB*DM*NM];
__device__ float g_pred[NB*2*NS];
__device__ float g_part[16*NB*DIN > 4*NB*2*DM ? 16*NB*DIN : 4*NB*2*DM]; // split-K partials

// ---------------- helpers ----------------
__device__ __forceinline__ ull dup2(float x){
    ull r; unsigned u = __float_as_uint(x);
    asm("mov.b64 %0, {%1, %1};" : "=l"(r) : "r"(u));
    return r;
}
__device__ __forceinline__ ull pack2(float x, float y){
    ull r;
    asm("mov.b64 %0, {%1, %2};" : "=l"(r) : "r"(__float_as_uint(x)), "r"(__float_as_uint(y)));
    return r;
}
__device__ __forceinline__ float lo32(ull v){ return __uint_as_float((unsigned)(v & 0xffffffffull)); }
__device__ __forceinline__ float hi32(ull v){ return __uint_as_float((unsigned)(v >> 32)); }
#define FMA2(d,a,b) asm("fma.rn.f32x2 %0, %1, %2, %3;" : "=l"(d) : "l"(a), "l"(b), "l"(d))

__device__ __forceinline__ float blockReduce(float v, float* red, bool domax){
    int tid = threadIdx.x;
    #pragma unroll
    for (int o=16;o>0;o>>=1){
        float t = __shfl_xor_sync(0xffffffffu, v, o);
        v = domax ? fmaxf(v,t) : (v+t);
    }
    if ((tid&31)==0) red[tid>>5] = v;
    __syncthreads();
    if (tid < 32){
        float x = (tid < 8) ? red[tid] : (domax ? -3.4e38f : 0.f);
        #pragma unroll
        for (int o=4;o>0;o>>=1){
            float t = __shfl_xor_sync(0xffffffffu, x, o);
            x = domax ? fmaxf(x,t) : (x+t);
        }
        if (tid==0) red[0]=x;
    }
    __syncthreads();
    float out = red[0];
    __syncthreads();
    return out;
}

// ---------------- fp32x2 GEMM, double-buffered, conflict-free ----------------
// C[m,n] = A[m,k]*B[k,n] (+bias). BM=128, BK=8, 256 threads.
// BN=128 -> 8x8/thread; BN=64 -> 8x4/thread. Split rows/cols into two
// half-tile groups for conflict-free LDS.
// grid.x = mTiles*nTiles, grid.y = K-splits (writes C + y*splitStride), grid.z = batch.
template<int BN, int TN>
__global__ void __launch_bounds__(256,2)
gemm_t(const float* __restrict__ A, const float* __restrict__ B,
       const float* __restrict__ bias, float* __restrict__ C,
       int Kchunk, int lda, int ldb, int ldc,
       long sA, long sB, long sC, int nTiles, long splitStride)
{
    A += (long)blockIdx.z * sA;
    B += (long)blockIdx.z * sB;
    C += (long)blockIdx.z * sC + (long)blockIdx.y * splitStride;
    int mt = blockIdx.x / nTiles;
    int nt = blockIdx.x - mt*nTiles;
    int m0 = mt*128, n0 = nt*BN;
    int k0 = blockIdx.y * Kchunk;

    __shared__ float As[2][8][132];
    __shared__ float Bs[2][8][BN];
    int tid = threadIdx.x;
    const int NCOL = BN / TN;             // 16
    int tx = tid % NCOL, ty = tid / NCOL; // both 0..15

    int aRow = tid >> 1, aCol = (tid & 1)*4;
    const float* Ap = A + (long)(m0 + aRow)*lda + k0 + aCol;
    int bRow = tid >> 5;
    int bCol = (BN == 128) ? (tid & 31)*4 : (tid & 31)*2;
    const float* Bp = B + (long)(k0 + bRow)*ldb + n0 + bCol;

    ull acc[8][TN/2];
    #pragma unroll
    for (int i=0;i<8;i++)
        #pragma unroll
        for (int j=0;j<TN/2;j++) acc[i][j] = 0ull;

    float4 a_nxt = *(const float4*)Ap;
    float4 b_nxt4; float2 b_nxt2;
    if constexpr (BN == 128) b_nxt4 = *(const float4*)Bp;
    else                     b_nxt2 = *(const float2*)Bp;

    // store buf 0
    As[0][aCol+0][aRow]=a_nxt.x; As[0][aCol+1][aRow]=a_nxt.y;
    As[0][aCol+2][aRow]=a_nxt.z; As[0][aCol+3][aRow]=a_nxt.w;
    if constexpr (BN == 128) *(float4*)&Bs[0][bRow][bCol] = b_nxt4;
    else                     *(float2*)&Bs[0][bRow][bCol] = b_nxt2;
    __syncthreads();

    int buf = 0;
    for (int kk=8; kk<Kchunk; kk+=8){
        a_nxt = *(const float4*)(Ap + kk);
        if constexpr (BN == 128) b_nxt4 = *(const float4*)(Bp + (long)kk*ldb);
        else                     b_nxt2 = *(const float2*)(Bp + (long)kk*ldb);
        // compute on buf
        #pragma unroll
        for (int k=0;k<8;k++){
            float4 a0 = *(const float4*)&As[buf][k][ty*4];
            float4 a1 = *(const float4*)&As[buf][k][64+ty*4];
            ull bp[TN/2];
            if constexpr (BN == 128){
                float4 b0 = *(const float4*)&Bs[buf][k][tx*4];
                float4 b1 = *(const float4*)&Bs[buf][k][64+tx*4];
                bp[0]=pack2(b0.x,b0.y); bp[1]=pack2(b0.z,b0.w);
                bp[2]=pack2(b1.x,b1.y); bp[3]=pack2(b1.z,b1.w);
            } else {
                float2 b0 = *(const float2*)&Bs[buf][k][tx*2];
                float2 b1 = *(const float2*)&Bs[buf][k][32+tx*2];
                bp[0]=pack2(b0.x,b0.y); bp[1]=pack2(b1.x,b1.y);
            }
            float am[8] = {a0.x,a0.y,a0.z,a0.w,a1.x,a1.y,a1.z,a1.w};
            #pragma unroll
            for (int i=0;i<8;i++){
                ull ad = dup2(am[i]);
                #pragma unroll
                for (int j=0;j<TN/2;j++) FMA2(acc[i][j], ad, bp[j]);
            }
        }
        int nb = buf ^ 1;
        As[nb][aCol+0][aRow]=a_nxt.x; As[nb][aCol+1][aRow]=a_nxt.y;
        As[nb][aCol+2][aRow]=a_nxt.z; As[nb][aCol+3][aRow]=a_nxt.w;
        if constexpr (BN == 128) *(float4*)&Bs[nb][bRow][bCol] = b_nxt4;
        else                     *(float2*)&Bs[nb][bRow][bCol] = b_nxt2;
        __syncthreads();
        buf = nb;
    }
    // last tile
    #pragma unroll
    for (int k=0;k<8;k++){
        float4 a0 = *(const float4*)&As[buf][k][ty*4];
        float4 a1 = *(const float4*)&As[buf][k][64+ty*4];
        ull bp[TN/2];
        if constexpr (BN == 128){
            float4 b0 = *(const float4*)&Bs[buf][k][tx*4];
            float4 b1 = *(const float4*)&Bs[buf][k][64+tx*4];
            bp[0]=pack2(b0.x,b0.y); bp[1]=pack2(b0.z,b0.w);
            bp[2]=pack2(b1.x,b1.y); bp[3]=pack2(b1.z,b1.w);
        } else {
            float2 b0 = *(const float2*)&Bs[buf][k][tx*2];
            float2 b1 = *(const float2*)&Bs[buf][k][32+tx*2];
            bp[0]=pack2(b0.x,b0.y); bp[1]=pack2(b1.x,b1.y);
        }
        float am[8] = {a0.x,a0.y,a0.z,a0.w,a1.x,a1.y,a1.z,a1.w};
        #pragma unroll
        for (int i=0;i<8;i++){
            ull ad = dup2(am[i]);
            #pragma unroll
            for (int j=0;j<TN/2;j++) FMA2(acc[i][j], ad, bp[j]);
        }
    }

    // epilogue: two row groups x two col groups, vectorized stores
    #pragma unroll
    for (int i=0;i<8;i++){
        int row = m0 + ((i<4) ? (ty*4 + i) : (64 + ty*4 + (i-4)));
        if constexpr (BN == 128){
            int c0 = n0 + tx*4, c1 = n0 + 64 + tx*4;
            float4 v0 = make_float4(lo32(acc[i][0]), hi32(acc[i][0]),
                                    lo32(acc[i][1]), hi32(acc[i][1]));
            float4 v1 = make_float4(lo32(acc[i][2]), hi32(acc[i][2]),
                                    lo32(acc[i][3]), hi32(acc[i][3]));
            if (bias){
                float4 q0 = *(const float4*)&bias[c0];
                float4 q1 = *(const float4*)&bias[c1];
                v0.x+=q0.x; v0.y+=q0.y; v0.z+=q0.z; v0.w+=q0.w;
                v1.x+=q1.x; v1.y+=q1.y; v1.z+=q1.z; v1.w+=q1.w;
            }
            *(float4*)&C[(long)row*ldc + c0] = v0;
            *(float4*)&C[(long)row*ldc + c1] = v1;
        } else {
            int c0 = n0 + tx*2, c1 = n0 + 32 + tx*2;
            float2 v0 = make_float2(lo32(acc[i][0]), hi32(acc[i][0]));
            float2 v1 = make_float2(lo32(acc[i][1]), hi32(acc[i][1]));
            if (bias){
                float2 q0 = *(const float2*)&bias[c0];
                float2 q1 = *(const float2*)&bias[c1];
                v0.x+=q0.x; v0.y+=q0.y; v1.x+=q1.x; v1.y+=q1.y;
            }
            *(float2*)&C[(long)row*ldc + c0] = v0;
            *(float2*)&C[(long)row*ldc + c1] = v1;
        }
    }
}

// sum nsplit partial buffers + bias -> dst
__global__ void reduce_k(const float* __restrict__ src, float* __restrict__ dst,
                         const float* __restrict__ bias, int N, int total,
                         int nsplit, long sStride){
    int i4 = (blockIdx.x*256 + threadIdx.x)*4;
    if (i4 >= total) return;
    float4 acc = make_float4(0.f,0.f,0.f,0.f);
    if (bias){
        acc = *(const float4*)&bias[i4 % N];
    }
    for (int s=0;s<nsplit;s++){
        float4 v = *(const float4*)&src[s*sStride + i4];
        acc.x+=v.x; acc.y+=v.y; acc.z+=v.z; acc.w+=v.w;
    }
    *(float4*)&dst[i4] = acc;
}

// ---------------- small kernels ----------------
__global__ void iuju_init(){
    int i = threadIdx.x;
    if (i < 64){
        int off = i*64 - (i*(i-1))/2;
        for (int j=i;j<64;j++){ g_iu[off+j-i]=i; g_ju[off+j-i]=j; }
    }
}

__global__ void fkern(const float* __restrict__ Wpos, const float* __restrict__ bpos,
                      const float* __restrict__ emb){
    int i = blockIdx.x*256+threadIdx.x;
    if (i >= NS*DIN) return;
    int s = i >> 9, d = i & 511;
    float fr = (float)s / (float)(NS-1);
    float sn, cs; sincospif(fr, &sn, &cs);
    float pe = -sn*Wpos[d] + cs*Wpos[DIN+d] + bpos[d];
    g_F[i]            = emb[d]       + pe;
    g_F[NS*DIN + i]   = emb[DIN + d] + pe;
}

__global__ void transp(){
    int z = blockIdx.z;
    const float* src = g_tmp + (long)z*NS*DIN;
    float* dst = g_KT + (long)z*DIN*NS;
    __shared__ float tile[32][33];
    int s0 = blockIdx.x*32, n0 = blockIdx.y*32;
    int x = threadIdx.x, y = threadIdx.y;
    #pragma unroll
    for (int r=0;r<32;r+=8) tile[y+r][x] = src[(s0+y+r)*DIN + n0 + x];
    __syncthreads();
    #pragma unroll
    for (int r=0;r<32;r+=8) dst[(n0+y+r)*NS + s0 + x] = tile[x][y+r];
}

__global__ void reshV(){
    int i = blockIdx.x*256+threadIdx.x;
    if (i >= 2*NS*DIN) return;
    int tok = i / (NS*DIN);
    int rem = i - tok*(NS*DIN);
    int s = rem >> 9, n = rem & 511;
    int h = n >> 6, d = n & 63;
    g_Vc[(((h*2 + tok)*NS) + s)*64 + d] = g_tmp[i];
}

__global__ void init_state(const float* __restrict__ sa, const float* __restrict__ st){
    int i = blockIdx.x*256+threadIdx.x;
    if (i < NB*DM) g_act[i] = sa[i & (DM-1)];
    if (i < NB*DM*NM){
        int rem = i % (DM*NM);
        g_ring[i] = st[rem];
    }
}

__global__ void sync_k(const float* __restrict__ decay, float* __restrict__ alpha,
                       int base, int t){
    int b = blockIdx.x;
    __shared__ float sel[64];
    int tid = threadIdx.x;
    if (tid < 64) sel[tid] = g_act[b*DM + base + tid];
    __syncthreads();
    for (int p=tid; p<NREP; p+=256){
        float pair = sel[g_iu[p]] * sel[g_ju[p]];
        float r = expf(-decay[p]);
        float al = (t==0) ? pair : fmaf(r, alpha[b*NREP+p], pair);
        alpha[b*NREP+p] = al;
        float bet = 1.f;
        for (int k=0;k<t;k++) bet = fmaf(r, bet, 1.f);
        g_s[b*NREP+p] = al * rsqrtf(bet);
    }
}

__global__ void __launch_bounds__(256) softmax_sel(const int* __restrict__ tokens){
    int b = blockIdx.x, h = blockIdx.y;
    __shared__ float sv[NS];
    __shared__ unsigned char tks[NS];
    __shared__ float red[8];
    int tid = threadIdx.x;
    float mx = -3.4e38f;
    for (int s=tid;s<NS;s+=256){
        int tk = tokens[b*NS+s];
        float v = g_D[(((tk*NH + h)*NB) + b)*NS + s] * 0.125f;
        sv[s]=v; tks[s]=(unsigned char)tk;
        mx = fmaxf(mx,v);
    }
    mx = blockReduce(mx, red, true);
    float sum=0.f;
    for (int s=tid;s<NS;s+=256){ float e = expf(sv[s]-mx); sv[s]=e; sum+=e; }
    sum = blockReduce(sum, red, false);
    float inv = 1.f/sum;
    long base = ((long)b*NH + h)*2*NS;
    for (int s=tid;s<NS;s+=256){
        int tk = tks[s];
        g_attn[base + tk*NS + s]     = sv[s]*inv;
        g_attn[base + (1-tk)*NS + s] = 0.f;
    }
}

__global__ void concat_k(){
    int i = blockIdx.x*256+threadIdx.x;
    if (i >= NB*(DIN+DM)) return;
    int b = i / (DIN+DM), c = i - b*(DIN+DM);
    g_cat[i] = (c < DIN) ? g_o2[b*DIN + c] : g_act[b*DM + (c - DIN)];
}

__global__ void __launch_bounds__(256) glu_ln(const float* __restrict__ g,
                                              const float* __restrict__ bb){
    int b = blockIdx.x, tid = threadIdx.x;
    __shared__ float v[DM];
    __shared__ float red[8];
    float lsum=0.f;
    for (int n=tid;n<DM;n+=256){
        float g1 = g_pre[b*2*DM + n];
        float g2 = g_pre[b*2*DM + DM + n];
        float x = g1 / (1.f + expf(-g2));
        v[n]=x; lsum+=x;
    }
    float mu = blockReduce(lsum, red, false) * (1.f/DM);
    float lv=0.f;
    for (int n=tid;n<DM;n+=256){ float d0=v[n]-mu; lv = fmaf(d0,d0,lv); }
    float var = blockReduce(lv, red, false) * (1.f/DM);
    float rs = rsqrtf(var + 1e-5f);
    for (int n=tid;n<DM;n+=256)
        g_state[b*DM+n] = (v[n]-mu)*rs*g[n] + bb[n];
}

__global__ void trace_act(const float* __restrict__ lg, const float* __restrict__ lb,
                          const float* __restrict__ Wn, const float* __restrict__ bn,
                          const float* __restrict__ temp, int t){
    int b = blockIdx.x;
    int n = blockIdx.y*256 + threadIdx.x;
    float* ring = &g_ring[((long)b*DM + n)*NM];
    ring[t % NM] = g_state[b*DM + n];
    float vals[NM];
    float mu = 0.f;
    #pragma unroll
    for (int m=0;m<NM;m++){
        int slot = (t+1+m) % NM;
        vals[m] = ring[slot];
        mu += vals[m];
    }
    mu *= (1.f/NM);
    float var = 0.f;
    #pragma unroll
    for (int m=0;m<NM;m++){ float d0 = vals[m]-mu; var = fmaf(d0,d0,var); }
    var *= (1.f/NM);
    float rs = rsqrtf(var + 1e-5f);
    float y0 = bn[n*2+0], y1 = bn[n*2+1];
    #pragma unroll
    for (int m=0;m<NM;m++){
        float xn = (vals[m]-mu)*rs*lg[m] + lb[m];
        y0 = fmaf(xn, Wn[(m*2+0)*DM + n], y0);
        y1 = fmaf(xn, Wn[(m*2+1)*DM + n], y1);
    }
    g_act[b*DM + n] = y0 * (1.f/(1.f + expf(-y1))) / temp[0];
}

__global__ void __launch_bounds__(256) finalize(float* __restrict__ out, int t){
    int b = blockIdx.x, tid = threadIdx.x;
    __shared__ float red[8];
    float sum = 0.f;
    for (int s=tid; s<NS; s+=256){
        float l0 = g_pred[b*4096 + 2*s];
        float l1 = g_pred[b*4096 + 2*s + 1];
        out[((long)b*4096 + 2*s)*NT + t]     = l0;
        out[((long)b*4096 + 2*s + 1)*NT + t] = l1;
        float m = fmaxf(l0,l1);
        float e0 = expf(l0-m), e1 = expf(l1-m);
        float Z = e0+e1;
        float ent = (logf(Z) - (e0*(l0-m) + e1*(l1-m))/Z) * 1.4426950408889634f;
        sum += ent;
    }
    sum = blockReduce(sum, red, false);
    if (tid == 0){
        float ne = sum * (1.f/NS);
        float* certs = out + (long)NB*4096*NT;
        certs[(b*2+0)*NT + t] = ne;
        certs[(b*2+1)*NT + t] = 1.f - ne;
    }
}

// ---------------- host ----------------
extern "C" void kernel_launch(void* const* d_in, const int* in_sizes, int n_in,
                              void* d_out, int out_size) {
    const int*   tokens = (const int*)  d_in[0];
    const float* emb    = (const float*)d_in[1];
    const float* W_pos  = (const float*)d_in[2];
    const float* b_pos  = (const float*)d_in[3];
    const float* Wq     = (const float*)d_in[4];
    const float* bq     = (const float*)d_in[5];
    const float* Wk     = (const float*)d_in[6];
    const float* bk     = (const float*)d_in[7];
    const float* Wv     = (const float*)d_in[8];
    const float* bv     = (const float*)d_in[9];
    const float* Wo     = (const float*)d_in[10];
    const float* bo     = (const float*)d_in[11];
    const float* Ws     = (const float*)d_in[12];
    const float* bs     = (const float*)d_in[13];
    const float* ln_s_g = (const float*)d_in[14];
    const float* ln_s_b = (const float*)d_in[15];
    const float* ln_n_g = (const float*)d_in[16];
    const float* ln_n_b = (const float*)d_in[17];
    const float* Wn     = (const float*)d_in[18];
    const float* bn     = (const float*)d_in[19];
    const float* temp   = (const float*)d_in[20];
    const float* Wout   = (const float*)d_in[21];
    const float* bout   = (const float*)d_in[22];
    const float* s_act  = (const float*)d_in[23];
    const float* s_tr   = (const float*)d_in[24];
    const float* dec_a  = (const float*)d_in[25];
    const float* dec_o  = (const float*)d_in[26];
    float* out = (float*)d_out;

    float *F,*tmp,*KT,*Vc,*al_a,*al_o,*sp,*qp,*Dp,*attnp,*o1p,*o2p,*catp,*prep,*predp,*part;
    cudaGetSymbolAddress((void**)&F,    g_F);
    cudaGetSymbolAddress((void**)&tmp,  g_tmp);
    cudaGetSymbolAddress((void**)&KT,   g_KT);
    cudaGetSymbolAddress((void**)&Vc,   g_Vc);
    cudaGetSymbolAddress((void**)&al_a, g_alpha_a);
    cudaGetSymbolAddress((void**)&al_o, g_alpha_o);
    cudaGetSymbolAddress((void**)&sp,   g_s);
    cudaGetSymbolAddress((void**)&qp,   g_q);
    cudaGetSymbolAddress((void**)&Dp,   g_D);
    cudaGetSymbolAddress((void**)&attnp,g_attn);
    cudaGetSymbolAddress((void**)&o1p,  g_o1);
    cudaGetSymbolAddress((void**)&o2p,  g_o2);
    cudaGetSymbolAddress((void**)&catp, g_cat);
    cudaGetSymbolAddress((void**)&prep, g_pre);
    cudaGetSymbolAddress((void**)&predp,g_pred);
    cudaGetSymbolAddress((void**)&part, g_part);

    // -------- precompute --------
    iuju_init<<<1,64>>>();
    fkern<<<(NS*DIN)/256, 256>>>(W_pos, b_pos, emb);
    // K projections: z in {tok0, tok1}: M=2048, N=512, K=512
    gemm_t<128,8><<<dim3(16*4,1,2),256>>>(F, Wk, bk, tmp, 512, 512,512,512,
            (long)NS*DIN, 0, (long)NS*DIN, 4, 0);
    transp<<<dim3(64,16,2),dim3(32,8)>>>();
    // V projections
    gemm_t<128,8><<<dim3(16*4,1,2),256>>>(F, Wv, bv, tmp, 512, 512,512,512,
            (long)NS*DIN, 0, (long)NS*DIN, 4, 0);
    reshV<<<(2*NS*DIN)/256,256>>>();
    init_state<<<(NB*DM*NM + 255)/256, 256>>>(s_act, s_tr);

    // -------- T iterations --------
    for (int t=0; t<NT; t++){
        // sync over action neurons (last 64 of act)
        sync_k<<<NB,256>>>(dec_a, al_a, DM-64, t);
        // q = s @ Wq + bq : M=128, N=512, K=2080 -> 13 splits x 160
        gemm_t<64,4><<<dim3(8,13,1),256>>>(sp, Wq, nullptr, part, 160,
                NREP, DIN, DIN, 0,0,0, 8, (long)NB*DIN);
        reduce_k<<<(NB*DIN)/1024,256>>>(part, qp, bq, DIN, NB*DIN, 13, (long)NB*DIN);
        // scores: per (tok, h): M=128, N=2048, K=64 (z = h)
        for (int tok=0; tok<2; tok++){
            gemm_t<128,8><<<dim3(16,1,NH),256>>>(
                qp, KT + (long)tok*DIN*NS, nullptr, Dp + (long)tok*NH*NB*NS,
                64, DIN, NS, NS, 64L, 64L*NS, (long)NB*NS, 16, 0);
        }
        softmax_sel<<<dim3(NB,NH),256>>>(tokens);
        // o1: per h: M=128, N=64, K=4096 -> 16 splits x 256
        gemm_t<64,4><<<dim3(1,16,NH),256>>>(attnp, Vc, nullptr, part, 256,
                NH*2*NS, 64, DIN, 2L*NS, 2L*NS*64, 64L, 1, (long)NB*DIN);
        reduce_k<<<(NB*DIN)/1024,256>>>(part, o1p, nullptr, DIN, NB*DIN, 16, (long)NB*DIN);
        // o2 = o1 @ Wo + bo : M=128, N=512, K=512 -> 4 splits x 128
        gemm_t<64,4><<<dim3(8,4,1),256>>>(o1p, Wo, nullptr, part, 128,
                DIN, DIN, DIN, 0,0,0, 8, (long)NB*DIN);
        reduce_k<<<(NB*DIN)/1024,256>>>(part, o2p, bo, DIN, NB*DIN, 4, (long)NB*DIN);
        concat_k<<<(NB*(DIN+DM))/256,256>>>();
        // pre = cat @ Ws + bs : M=128, N=4096, K=2560 -> 4 splits x 640
        gemm_t<128,8><<<dim3(32,4,1),256>>>(catp, Ws, nullptr, part, 640,
                DIN+DM, 2*DM, 2*DM, 0,0,0, 32, (long)NB*2*DM);
        reduce_k<<<(NB*2*DM)/1024,256>>>(part, prep, bs, 2*DM, NB*2*DM, 4, (long)NB*2*DM);
        glu_ln<<<NB,256>>>(ln_s_g, ln_s_b);
        trace_act<<<dim3(NB,DM/256),256>>>(ln_n_g, ln_n_b, Wn, bn, temp, t);
        // sync over output neurons (first 64 of act)
        sync_k<<<NB,256>>>(dec_o, al_o, 0, t);
        // pred = s @ Wout + bout : M=128, N=4096, K=2080 -> 4 splits x 520
        gemm_t<128,8><<<dim3(32,4,1),256>>>(sp, Wout, nullptr, part, 520,
                NREP, 2*NS, 2*NS, 0,0,0, 32, (long)NB*2*NS);
        reduce_k<<<(NB*2*NS)/1024,256>>>(part, predp, bout, 2*NS, NB*2*NS, 4, (long)NB*2*NS);
        finalize<<<NB,256>>>(out, t);
    }
}

// round 9
// speedup vs baseline: 2.0747x; 1.1880x over previous
#include <cuda_runtime.h>
#include <cuda_bf16.h>
#include <math.h>
#include <stdint.h>

#define NB   128
#define NS   2048
#define DIN  512
#define DM   2048
#define NM   25
#define NH   8
#define NT   10
#define NREP 2080
#define PADH 72   // halves per smem row (64 data + 8 pad)

typedef unsigned long long ull;

// ---------------- scratch (device globals; no allocation allowed) ------------
__device__ float g_F[2*NS*DIN];
__device__ float g_tmp[2*NS*DIN];
__device__ float g_KT[2*DIN*NS];          // [tok][n=h*64+d][s]
__device__ float g_Vc[NH*2*NS*64];        // [h][tok][s][d]
__device__ int   g_iu[NREP], g_ju[NREP];
__device__ float g_act[NB*DM];
__device__ float g_alpha_a[NB*NREP];
__device__ float g_alpha_o[NB*NREP];
__device__ float g_s[NB*NREP];
__device__ float g_q[NB*DIN];
__device__ float g_D[2*NH*NB*NS];         // [tok][h][b][s]
__device__ float g_attn[NB*NH*2*NS];      // [b][h][tok][s]
__device__ float g_o1[NB*DIN];
__device__ float g_o2[NB*DIN];
__device__ float g_cat[NB*(DIN+DM)];
__device__ float g_pre[NB*2*DM];
__device__ float g_state[NB*DM];
__device__ float g_ring[NB*DM*NM];
__device__ float g_pred[NB*2*NS];
__device__ float g_part[16*NB*DIN > 4*NB*2*DM ? 16*NB*DIN : 4*NB*2*DM]; // split-K partials

// bf16x3 tensor-core buffers
__device__ __nv_bfloat16 g_BTpre [4096L*5120];   // Ws^T  [n][2*2560] (hi|lo)
__device__ __nv_bfloat16 g_BTpred[4096L*4224];   // Wout^T[n][2*2112] (hi|lo, zero-padded)
__device__ __nv_bfloat16 g_Abf   [128L*5120];    // activations hi|lo

// ---------------- helpers ----------------
__device__ __forceinline__ ull dup2(float x){
    ull r; unsigned u = __float_as_uint(x);
    asm("mov.b64 %0, {%1, %1};" : "=l"(r) : "r"(u));
    return r;
}
__device__ __forceinline__ ull pack2(float x, float y){
    ull r;
    asm("mov.b64 %0, {%1, %2};" : "=l"(r) : "r"(__float_as_uint(x)), "r"(__float_as_uint(y)));
    return r;
}
__device__ __forceinline__ float lo32(ull v){ return __uint_as_float((unsigned)(v & 0xffffffffull)); }
__device__ __forceinline__ float hi32(ull v){ return __uint_as_float((unsigned)(v >> 32)); }
#define FMA2(d,a,b) asm("fma.rn.f32x2 %0, %1, %2, %3;" : "=l"(d) : "l"(a), "l"(b), "l"(d))

__device__ __forceinline__ float blockReduce(float v, float* red, bool domax){
    int tid = threadIdx.x;
    #pragma unroll
    for (int o=16;o>0;o>>=1){
        float t = __shfl_xor_sync(0xffffffffu, v, o);
        v = domax ? fmaxf(v,t) : (v+t);
    }
    if ((tid&31)==0) red[tid>>5] = v;
    __syncthreads();
    if (tid < 32){
        float x = (tid < 8) ? red[tid] : (domax ? -3.4e38f : 0.f);
        #pragma unroll
        for (int o=4;o>0;o>>=1){
            float t = __shfl_xor_sync(0xffffffffu, x, o);
            x = domax ? fmaxf(x,t) : (x+t);
        }
        if (tid==0) red[0]=x;
    }
    __syncthreads();
    float out = red[0];
    __syncthreads();
    return out;
}

__device__ __forceinline__ void cpasync16(void* s, const void* g){
    uint32_t sa = (uint32_t)__cvta_generic_to_shared(s);
    asm volatile("cp.async.cg.shared.global [%0], [%1], 16;" :: "r"(sa), "l"(g));
}

#define MMA_BF16(d, a0,a1,a2,a3, b0,b1) \
    asm volatile("mma.sync.aligned.m16n8k16.row.col.f32.bf16.bf16.f32 " \
        "{%0,%1,%2,%3}, {%4,%5,%6,%7}, {%8,%9}, {%0,%1,%2,%3};" \
        : "+f"((d)[0]), "+f"((d)[1]), "+f"((d)[2]), "+f"((d)[3]) \
        : "r"(a0), "r"(a1), "r"(a2), "r"(a3), "r"(b0), "r"(b1))

// ---------------- mma.sync bf16x3 GEMM ----------------
// D[128, 128-tile] = sum over composite chunk list of A(128xKpad2) @ B^T tiles.
// Chunk idx -> pass p = idx/nchp (0:hh 1:hl 2:lh), c = idx%nchp (64-half chunks).
// grid.x = N/128 tiles, grid.y = K splits. Writes partials (no bias).
__global__ void __launch_bounds__(256,1)
gemm_mma(const __nv_bfloat16* __restrict__ Ab, const __nv_bfloat16* __restrict__ Bb,
         float* __restrict__ Cpart, int Kpad, int totChunks, int cps, int ldc)
{
    extern __shared__ __nv_bfloat16 sm[];
    int tid = threadIdx.x, lane = tid&31, wid = tid>>5;
    int grp = lane>>2, qp = lane&3;
    int wm = wid>>2, wn = wid&3;          // warp tile: 64x32
    int n0 = blockIdx.x*128;
    int c0 = blockIdx.y*cps;
    int nck = min(cps, totChunks - c0);
    int nchp = Kpad >> 6;
    long Kpad2 = 2L*Kpad;
    Cpart += (long)blockIdx.y*128L*ldc;

    float acc[4][4][4];
    #pragma unroll
    for (int a=0;a<4;a++)
        #pragma unroll
        for (int b=0;b<4;b++)
            #pragma unroll
            for (int c=0;c<4;c++) acc[a][b][c]=0.f;

    auto prefetch = [&](int idx, int buf){
        __nv_bfloat16* As = sm + buf*(2*128*PADH);
        __nv_bfloat16* Bs = As + 128*PADH;
        int pass = idx / nchp, c = idx - pass*nchp;
        long kA = ((pass==2)?(long)Kpad:0L) + (long)c*64;
        long kB = ((pass==1)?(long)Kpad:0L) + (long)c*64;
        #pragma unroll
        for (int it=0; it<4; it++){
            int li = tid + it*256;        // 0..1023
            int r = li>>3, seg = li&7;
            cpasync16(As + r*PADH + seg*8, Ab + (long)r*Kpad2 + kA + seg*8);
            cpasync16(Bs + r*PADH + seg*8, Bb + (long)(n0+r)*Kpad2 + kB + seg*8);
        }
        asm volatile("cp.async.commit_group;" ::: "memory");
    };

    prefetch(c0, 0);
    for (int i=0;i<nck;i++){
        asm volatile("cp.async.wait_group 0;" ::: "memory");
        __syncthreads();
        if (i+1 < nck) prefetch(c0+i+1, (i+1)&1);
        const __nv_bfloat16* As = sm + (i&1)*(2*128*PADH);
        const __nv_bfloat16* Bs = As + 128*PADH;
        #pragma unroll
        for (int ks=0; ks<4; ks++){
            int kh = ks*16 + qp*2;        // half offset within row
            uint32_t bfr[4][2];
            #pragma unroll
            for (int nt=0;nt<4;nt++){
                int col = wn*32 + nt*8 + grp;
                bfr[nt][0] = *(const uint32_t*)(Bs + col*PADH + kh);
                bfr[nt][1] = *(const uint32_t*)(Bs + col*PADH + kh + 8);
            }
            #pragma unroll
            for (int mt=0;mt<4;mt++){
                int row = wm*64 + mt*16 + grp;
                uint32_t a0 = *(const uint32_t*)(As + row*PADH + kh);
                uint32_t a1 = *(const uint32_t*)(As + (row+8)*PADH + kh);
                uint32_t a2 = *(const uint32_t*)(As + row*PADH + kh + 8);
                uint32_t a3 = *(const uint32_t*)(As + (row+8)*PADH + kh + 8);
                #pragma unroll
                for (int nt=0;nt<4;nt++)
                    MMA_BF16(acc[mt][nt], a0,a1,a2,a3, bfr[nt][0], bfr[nt][1]);
            }
        }
    }

    // epilogue
    #pragma unroll
    for (int mt=0;mt<4;mt++){
        int row = wm*64 + mt*16 + grp;
        #pragma unroll
        for (int nt=0;nt<4;nt++){
            int col = n0 + wn*32 + nt*8 + qp*2;
            *(float2*)&Cpart[(long)row*ldc + col]     = make_float2(acc[mt][nt][0], acc[mt][nt][1]);
            *(float2*)&Cpart[(long)(row+8)*ldc + col] = make_float2(acc[mt][nt][2], acc[mt][nt][3]);
        }
    }
}

// weight -> transposed hi/lo bf16 [N][2*Kpad]
__global__ void convB(const float* __restrict__ W, __nv_bfloat16* __restrict__ BT,
                      int K, int Kpad, int N){
    long i = (long)blockIdx.x*256 + threadIdx.x;
    if (i >= (long)N*Kpad) return;
    int nI = (int)(i / Kpad), k = (int)(i - (long)nI*Kpad);
    float x = (k < K) ? W[(long)k*N + nI] : 0.f;
    __nv_bfloat16 h = __float2bfloat16(x);
    float lo = x - __bfloat162float(h);
    BT[(long)nI*2*Kpad + k]        = h;
    BT[(long)nI*2*Kpad + Kpad + k] = __float2bfloat16(lo);
}

// activations -> hi/lo bf16 [128][2*Kpad]
__global__ void convA(const float* __restrict__ A, __nv_bfloat16* __restrict__ Ab,
                      int K, int Kpad){
    int i = blockIdx.x*256 + threadIdx.x;
    if (i >= 128*Kpad) return;
    int r = i / Kpad, k = i - r*Kpad;
    float x = (k < K) ? A[(long)r*K + k] : 0.f;
    __nv_bfloat16 h = __float2bfloat16(x);
    Ab[(long)r*2*Kpad + k]        = h;
    Ab[(long)r*2*Kpad + Kpad + k] = __float2bfloat16(x - __bfloat162float(h));
}

// ---------------- fp32x2 GEMM (R4-proven) ----------------
template<int BN, int TN>
__global__ void __launch_bounds__(256,2)
gemm_t(const float* __restrict__ A, const float* __restrict__ B,
       const float* __restrict__ bias, float* __restrict__ C,
       int Kchunk, int lda, int ldb, int ldc,
       long sA, long sB, long sC, int nTiles, long splitStride)
{
    A += (long)blockIdx.z * sA;
    B += (long)blockIdx.z * sB;
    C += (long)blockIdx.z * sC + (long)blockIdx.y * splitStride;
    int mt = blockIdx.x / nTiles;
    int nt = blockIdx.x - mt*nTiles;
    int m0 = mt*128, n0 = nt*BN;
    int k0 = blockIdx.y * Kchunk;

    __shared__ float As[2][8][132];
    __shared__ float Bs[2][8][BN];
    int tid = threadIdx.x;
    const int NCOL = BN / TN;
    int tx = tid % NCOL, ty = tid / NCOL;

    int aRow = tid >> 1, aCol = (tid & 1)*4;
    const float* Ap = A + (long)(m0 + aRow)*lda + k0 + aCol;
    int bRow = tid >> 5;
    int bCol = (BN == 128) ? (tid & 31)*4 : (tid & 31)*2;
    const float* Bp = B + (long)(k0 + bRow)*ldb + n0 + bCol;

    ull acc[8][TN/2];
    #pragma unroll
    for (int i=0;i<8;i++)
        #pragma unroll
        for (int j=0;j<TN/2;j++) acc[i][j] = 0ull;

    float4 a_nxt = *(const float4*)Ap;
    float4 b_nxt4; float2 b_nxt2;
    if constexpr (BN == 128) b_nxt4 = *(const float4*)Bp;
    else                     b_nxt2 = *(const float2*)Bp;

    As[0][aCol+0][aRow]=a_nxt.x; As[0][aCol+1][aRow]=a_nxt.y;
    As[0][aCol+2][aRow]=a_nxt.z; As[0][aCol+3][aRow]=a_nxt.w;
    if constexpr (BN == 128) *(float4*)&Bs[0][bRow][bCol] = b_nxt4;
    else                     *(float2*)&Bs[0][bRow][bCol] = b_nxt2;
    __syncthreads();

    int buf = 0;
    for (int kk=8; kk<Kchunk; kk+=8){
        a_nxt = *(const float4*)(Ap + kk);
        if constexpr (BN == 128) b_nxt4 = *(const float4*)(Bp + (long)kk*ldb);
        else                     b_nxt2 = *(const float2*)(Bp + (long)kk*ldb);
        #pragma unroll
        for (int k=0;k<8;k++){
            float4 a0 = *(const float4*)&As[buf][k][ty*4];
            float4 a1 = *(const float4*)&As[buf][k][64+ty*4];
            ull bp[TN/2];
            if constexpr (BN == 128){
                float4 b0 = *(const float4*)&Bs[buf][k][tx*4];
                float4 b1 = *(const float4*)&Bs[buf][k][64+tx*4];
                bp[0]=pack2(b0.x,b0.y); bp[1]=pack2(b0.z,b0.w);
                bp[2]=pack2(b1.x,b1.y); bp[3]=pack2(b1.z,b1.w);
            } else {
                float2 b0 = *(const float2*)&Bs[buf][k][tx*2];
                float2 b1 = *(const float2*)&Bs[buf][k][32+tx*2];
                bp[0]=pack2(b0.x,b0.y); bp[1]=pack2(b1.x,b1.y);
            }
            float am[8] = {a0.x,a0.y,a0.z,a0.w,a1.x,a1.y,a1.z,a1.w};
            #pragma unroll
            for (int i=0;i<8;i++){
                ull ad = dup2(am[i]);
                #pragma unroll
                for (int j=0;j<TN/2;j++) FMA2(acc[i][j], ad, bp[j]);
            }
        }
        int nb = buf ^ 1;
        As[nb][aCol+0][aRow]=a_nxt.x; As[nb][aCol+1][aRow]=a_nxt.y;
        As[nb][aCol+2][aRow]=a_nxt.z; As[nb][aCol+3][aRow]=a_nxt.w;
        if constexpr (BN == 128) *(float4*)&Bs[nb][bRow][bCol] = b_nxt4;
        else                     *(float2*)&Bs[nb][bRow][bCol] = b_nxt2;
        __syncthreads();
        buf = nb;
    }
    #pragma unroll
    for (int k=0;k<8;k++){
        float4 a0 = *(const float4*)&As[buf][k][ty*4];
        float4 a1 = *(const float4*)&As[buf][k][64+ty*4];
        ull bp[TN/2];
        if constexpr (BN == 128){
            float4 b0 = *(const float4*)&Bs[buf][k][tx*4];
            float4 b1 = *(const float4*)&Bs[buf][k][64+tx*4];
            bp[0]=pack2(b0.x,b0.y); bp[1]=pack2(b0.z,b0.w);
            bp[2]=pack2(b1.x,b1.y); bp[3]=pack2(b1.z,b1.w);
        } else {
            float2 b0 = *(const float2*)&Bs[buf][k][tx*2];
            float2 b1 = *(const float2*)&Bs[buf][k][32+tx*2];
            bp[0]=pack2(b0.x,b0.y); bp[1]=pack2(b1.x,b1.y);
        }
        float am[8] = {a0.x,a0.y,a0.z,a0.w,a1.x,a1.y,a1.z,a1.w};
        #pragma unroll
        for (int i=0;i<8;i++){
            ull ad = dup2(am[i]);
            #pragma unroll
            for (int j=0;j<TN/2;j++) FMA2(acc[i][j], ad, bp[j]);
        }
    }

    #pragma unroll
    for (int i=0;i<8;i++){
        int row = m0 + ((i<4) ? (ty*4 + i) : (64 + ty*4 + (i-4)));
        if constexpr (BN == 128){
            int c0 = n0 + tx*4, c1 = n0 + 64 + tx*4;
            float4 v0 = make_float4(lo32(acc[i][0]), hi32(acc[i][0]),
                                    lo32(acc[i][1]), hi32(acc[i][1]));
            float4 v1 = make_float4(lo32(acc[i][2]), hi32(acc[i][2]),
                                    lo32(acc[i][3]), hi32(acc[i][3]));
            if (bias){
                float4 q0 = *(const float4*)&bias[c0];
                float4 q1 = *(const float4*)&bias[c1];
                v0.x+=q0.x; v0.y+=q0.y; v0.z+=q0.z; v0.w+=q0.w;
                v1.x+=q1.x; v1.y+=q1.y; v1.z+=q1.z; v1.w+=q1.w;
            }
            *(float4*)&C[(long)row*ldc + c0] = v0;
            *(float4*)&C[(long)row*ldc + c1] = v1;
        } else {
            int c0 = n0 + tx*2, c1 = n0 + 32 + tx*2;
            float2 v0 = make_float2(lo32(acc[i][0]), hi32(acc[i][0]));
            float2 v1 = make_float2(lo32(acc[i][1]), hi32(acc[i][1]));
            if (bias){
                float2 q0 = *(const float2*)&bias[c0];
                float2 q1 = *(const float2*)&bias[c1];
                v0.x+=q0.x; v0.y+=q0.y; v1.x+=q1.x; v1.y+=q1.y;
            }
            *(float2*)&C[(long)row*ldc + c0] = v0;
            *(float2*)&C[(long)row*ldc + c1] = v1;
        }
    }
}

// sum nsplit partial buffers + bias -> dst
__global__ void reduce_k(const float* __restrict__ src, float* __restrict__ dst,
                         const float* __restrict__ bias, int N, int total,
                         int nsplit, long sStride){
    int i4 = (blockIdx.x*256 + threadIdx.x)*4;
    if (i4 >= total) return;
    float4 acc = make_float4(0.f,0.f,0.f,0.f);
    if (bias) acc = *(const float4*)&bias[i4 % N];
    for (int s=0;s<nsplit;s++){
        float4 v = *(const float4*)&src[s*sStride + i4];
        acc.x+=v.x; acc.y+=v.y; acc.z+=v.z; acc.w+=v.w;
    }
    *(float4*)&dst[i4] = acc;
}

// ---------------- small kernels ----------------
__global__ void iuju_init(){
    int i = threadIdx.x;
    if (i < 64){
        int off = i*64 - (i*(i-1))/2;
        for (int j=i;j<64;j++){ g_iu[off+j-i]=i; g_ju[off+j-i]=j; }
    }
}

__global__ void fkern(const float* __restrict__ Wpos, const float* __restrict__ bpos,
                      const float* __restrict__ emb){
    int i = blockIdx.x*256+threadIdx.x;
    if (i >= NS*DIN) return;
    int s = i >> 9, d = i & 511;
    float fr = (float)s / (float)(NS-1);
    float sn, cs; sincospif(fr, &sn, &cs);
    float pe = -sn*Wpos[d] + cs*Wpos[DIN+d] + bpos[d];
    g_F[i]            = emb[d]       + pe;
    g_F[NS*DIN + i]   = emb[DIN + d] + pe;
}

__global__ void transp(){
    int z = blockIdx.z;
    const float* src = g_tmp + (long)z*NS*DIN;
    float* dst = g_KT + (long)z*DIN*NS;
    __shared__ float tile[32][33];
    int s0 = blockIdx.x*32, n0 = blockIdx.y*32;
    int x = threadIdx.x, y = threadIdx.y;
    #pragma unroll
    for (int r=0;r<32;r+=8) tile[y+r][x] = src[(s0+y+r)*DIN + n0 + x];
    __syncthreads();
    #pragma unroll
    for (int r=0;r<32;r+=8) dst[(n0+y+r)*NS + s0 + x] = tile[x][y+r];
}

__global__ void reshV(){
    int i = blockIdx.x*256+threadIdx.x;
    if (i >= 2*NS*DIN) return;
    int tok = i / (NS*DIN);
    int rem = i - tok*(NS*DIN);
    int s = rem >> 9, n = rem & 511;
    int h = n >> 6, d = n & 63;
    g_Vc[(((h*2 + tok)*NS) + s)*64 + d] = g_tmp[i];
}

__global__ void init_state(const float* __restrict__ sa, const float* __restrict__ st){
    int i = blockIdx.x*256+threadIdx.x;
    if (i < NB*DM) g_act[i] = sa[i & (DM-1)];
    if (i < NB*DM*NM){
        int rem = i % (DM*NM);
        g_ring[i] = st[rem];
    }
}

__global__ void sync_k(const float* __restrict__ decay, float* __restrict__ alpha,
                       int base, int t){
    int b = blockIdx.x;
    __shared__ float sel[64];
    int tid = threadIdx.x;
    if (tid < 64) sel[tid] = g_act[b*DM + base + tid];
    __syncthreads();
    for (int p=tid; p<NREP; p+=256){
        float pair = sel[g_iu[p]] * sel[g_ju[p]];
        float r = expf(-decay[p]);
        float al = (t==0) ? pair : fmaf(r, alpha[b*NREP+p], pair);
        alpha[b*NREP+p] = al;
        float bet = 1.f;
        for (int k=0;k<t;k++) bet = fmaf(r, bet, 1.f);
        g_s[b*NREP+p] = al * rsqrtf(bet);
    }
}

__global__ void __launch_bounds__(256) softmax_sel(const int* __restrict__ tokens){
    int b = blockIdx.x, h = blockIdx.y;
    __shared__ float sv[NS];
    __shared__ unsigned char tks[NS];
    __shared__ float red[8];
    int tid = threadIdx.x;
    float mx = -3.4e38f;
    for (int s=tid;s<NS;s+=256){
        int tk = tokens[b*NS+s];
        float v = g_D[(((tk*NH + h)*NB) + b)*NS + s] * 0.125f;
        sv[s]=v; tks[s]=(unsigned char)tk;
        mx = fmaxf(mx,v);
    }
    mx = blockReduce(mx, red, true);
    float sum=0.f;
    for (int s=tid;s<NS;s+=256){ float e = expf(sv[s]-mx); sv[s]=e; sum+=e; }
    sum = blockReduce(sum, red, false);
    float inv = 1.f/sum;
    long base = ((long)b*NH + h)*2*NS;
    for (int s=tid;s<NS;s+=256){
        int tk = tks[s];
        g_attn[base + tk*NS + s]     = sv[s]*inv;
        g_attn[base + (1-tk)*NS + s] = 0.f;
    }
}

__global__ void concat_k(){
    int i = blockIdx.x*256+threadIdx.x;
    if (i >= NB*(DIN+DM)) return;
    int b = i / (DIN+DM), c = i - b*(DIN+DM);
    g_cat[i] = (c < DIN) ? g_o2[b*DIN + c] : g_act[b*DM + (c - DIN)];
}

__global__ void __launch_bounds__(256) glu_ln(const float* __restrict__ g,
                                              const float* __restrict__ bb){
    int b = blockIdx.x, tid = threadIdx.x;
    __shared__ float v[DM];
    __shared__ float red[8];
    float lsum=0.f;
    for (int n=tid;n<DM;n+=256){
        float g1 = g_pre[b*2*DM + n];
        float g2 = g_pre[b*2*DM + DM + n];
        float x = g1 / (1.f + expf(-g2));
        v[n]=x; lsum+=x;
    }
    float mu = blockReduce(lsum, red, false) * (1.f/DM);
    float lv=0.f;
    for (int n=tid;n<DM;n+=256){ float d0=v[n]-mu; lv = fmaf(d0,d0,lv); }
    float var = blockReduce(lv, red, false) * (1.f/DM);
    float rs = rsqrtf(var + 1e-5f);
    for (int n=tid;n<DM;n+=256)
        g_state[b*DM+n] = (v[n]-mu)*rs*g[n] + bb[n];
}

__global__ void trace_act(const float* __restrict__ lg, const float* __restrict__ lb,
                          const float* __restrict__ Wn, const float* __restrict__ bn,
                          const float* __restrict__ temp, int t){
    int b = blockIdx.x;
    int n = blockIdx.y*256 + threadIdx.x;
    float* ring = &g_ring[((long)b*DM + n)*NM];
    ring[t % NM] = g_state[b*DM + n];
    float vals[NM];
    float mu = 0.f;
    #pragma unroll
    for (int m=0;m<NM;m++){
        int slot = (t+1+m) % NM;
        vals[m] = ring[slot];
        mu += vals[m];
    }
    mu *= (1.f/NM);
    float var = 0.f;
    #pragma unroll
    for (int m=0;m<NM;m++){ float d0 = vals[m]-mu; var = fmaf(d0,d0,var); }
    var *= (1.f/NM);
    float rs = rsqrtf(var + 1e-5f);
    float y0 = bn[n*2+0], y1 = bn[n*2+1];
    #pragma unroll
    for (int m=0;m<NM;m++){
        float xn = (vals[m]-mu)*rs*lg[m] + lb[m];
        y0 = fmaf(xn, Wn[(m*2+0)*DM + n], y0);
        y1 = fmaf(xn, Wn[(m*2+1)*DM + n], y1);
    }
    g_act[b*DM + n] = y0 * (1.f/(1.f + expf(-y1))) / temp[0];
}

__global__ void __launch_bounds__(256) finalize(float* __restrict__ out, int t){
    int b = blockIdx.x, tid = threadIdx.x;
    __shared__ float red[8];
    float sum = 0.f;
    for (int s=tid; s<NS; s+=256){
        float l0 = g_pred[b*4096 + 2*s];
        float l1 = g_pred[b*4096 + 2*s + 1];
        out[((long)b*4096 + 2*s)*NT + t]     = l0;
        out[((long)b*4096 + 2*s + 1)*NT + t] = l1;
        float m = fmaxf(l0,l1);
        float e0 = expf(l0-m), e1 = expf(l1-m);
        float Z = e0+e1;
        float ent = (logf(Z) - (e0*(l0-m) + e1*(l1-m))/Z) * 1.4426950408889634f;
        sum += ent;
    }
    sum = blockReduce(sum, red, false);
    if (tid == 0){
        float ne = sum * (1.f/NS);
        float* certs = out + (long)NB*4096*NT;
        certs[(b*2+0)*NT + t] = ne;
        certs[(b*2+1)*NT + t] = 1.f - ne;
    }
}

// ---------------- host ----------------
extern "C" void kernel_launch(void* const* d_in, const int* in_sizes, int n_in,
                              void* d_out, int out_size) {
    const int*   tokens = (const int*)  d_in[0];
    const float* emb    = (const float*)d_in[1];
    const float* W_pos  = (const float*)d_in[2];
    const float* b_pos  = (const float*)d_in[3];
    const float* Wq     = (const float*)d_in[4];
    const float* bq     = (const float*)d_in[5];
    const float* Wk     = (const float*)d_in[6];
    const float* bk     = (const float*)d_in[7];
    const float* Wv     = (const float*)d_in[8];
    const float* bv     = (const float*)d_in[9];
    const float* Wo     = (const float*)d_in[10];
    const float* bo     = (const float*)d_in[11];
    const float* Ws     = (const float*)d_in[12];
    const float* bs     = (const float*)d_in[13];
    const float* ln_s_g = (const float*)d_in[14];
    const float* ln_s_b = (const float*)d_in[15];
    const float* ln_n_g = (const float*)d_in[16];
    const float* ln_n_b = (const float*)d_in[17];
    const float* Wn     = (const float*)d_in[18];
    const float* bn     = (const float*)d_in[19];
    const float* temp   = (const float*)d_in[20];
    const float* Wout   = (const float*)d_in[21];
    const float* bout   = (const float*)d_in[22];
    const float* s_act  = (const float*)d_in[23];
    const float* s_tr   = (const float*)d_in[24];
    const float* dec_a  = (const float*)d_in[25];
    const float* dec_o  = (const float*)d_in[26];
    float* out = (float*)d_out;

    float *F,*KT,*Vc,*al_a,*al_o,*sp,*qp,*Dp,*attnp,*o1p,*o2p,*catp,*prep,*predp,*part;
    __nv_bfloat16 *BTpre,*BTpred,*Abf;
    cudaGetSymbolAddress((void**)&F,    g_F);
    cudaGetSymbolAddress((void**)&KT,   g_KT);
    cudaGetSymbolAddress((void**)&Vc,   g_Vc);
    cudaGetSymbolAddress((void**)&al_a, g_alpha_a);
    cudaGetSymbolAddress((void**)&al_o, g_alpha_o);
    cudaGetSymbolAddress((void**)&sp,   g_s);
    cudaGetSymbolAddress((void**)&qp,   g_q);
    cudaGetSymbolAddress((void**)&Dp,   g_D);
    cudaGetSymbolAddress((void**)&attnp,g_attn);
    cudaGetSymbolAddress((void**)&o1p,  g_o1);
    cudaGetSymbolAddress((void**)&o2p,  g_o2);
    cudaGetSymbolAddress((void**)&catp, g_cat);
    cudaGetSymbolAddress((void**)&prep, g_pre);
    cudaGetSymbolAddress((void**)&predp,g_pred);
    cudaGetSymbolAddress((void**)&part, g_part);
    cudaGetSymbolAddress((void**)&BTpre, g_BTpre);
    cudaGetSymbolAddress((void**)&BTpred,g_BTpred);
    cudaGetSymbolAddress((void**)&Abf,  g_Abf);
    float* tmp; cudaGetSymbolAddress((void**)&tmp, g_tmp);

    const int MMA_SMEM = 4*128*PADH*2;   // 73728 bytes
    cudaFuncSetAttribute(gemm_mma, cudaFuncAttributeMaxDynamicSharedMemorySize, MMA_SMEM);

    // -------- precompute --------
    iuju_init<<<1,64>>>();
    fkern<<<(NS*DIN)/256, 256>>>(W_pos, b_pos, emb);
    gemm_t<128,8><<<dim3(16*4,1,2),256>>>(F, Wk, bk, tmp, 512, 512,512,512,
            (long)NS*DIN, 0, (long)NS*DIN, 4, 0);
    transp<<<dim3(64,16,2),dim3(32,8)>>>();
    gemm_t<128,8><<<dim3(16*4,1,2),256>>>(F, Wv, bv, tmp, 512, 512,512,512,
            (long)NS*DIN, 0, (long)NS*DIN, 4, 0);
    reshV<<<(2*NS*DIN)/256,256>>>();
    init_state<<<(NB*DM*NM + 255)/256, 256>>>(s_act, s_tr);
    // weight conversions (hi/lo bf16, transposed)
    convB<<<(int)((4096L*2560 + 255)/256),256>>>(Ws,   BTpre,  2560, 2560, 4096);
    convB<<<(int)((4096L*2112 + 255)/256),256>>>(Wout, BTpred, 2080, 2112, 4096);

    // -------- T iterations --------
    for (int t=0; t<NT; t++){
        sync_k<<<NB,256>>>(dec_a, al_a, DM-64, t);
        // q = s @ Wq + bq : fp32x2, 13 splits
        gemm_t<64,4><<<dim3(8,13,1),256>>>(sp, Wq, nullptr, part, 160,
                NREP, DIN, DIN, 0,0,0, 8, (long)NB*DIN);
        reduce_k<<<(NB*DIN)/1024,256>>>(part, qp, bq, DIN, NB*DIN, 13, (long)NB*DIN);
        // scores
        for (int tok=0; tok<2; tok++){
            gemm_t<128,8><<<dim3(16,1,NH),256>>>(
                qp, KT + (long)tok*DIN*NS, nullptr, Dp + (long)tok*NH*NB*NS,
                64, DIN, NS, NS, 64L, 64L*NS, (long)NB*NS, 16, 0);
        }
        softmax_sel<<<dim3(NB,NH),256>>>(tokens);
        // o1 : per h: M=128, N=64, K=4096 -> 16 splits x 256
        gemm_t<64,4><<<dim3(1,16,NH),256>>>(attnp, Vc, nullptr, part, 256,
                NH*2*NS, 64, DIN, 2L*NS, 2L*NS*64, 64L, 1, (long)NB*DIN);
        reduce_k<<<(NB*DIN)/1024,256>>>(part, o1p, nullptr, DIN, NB*DIN, 16, (long)NB*DIN);
        // o2
        gemm_t<64,4><<<dim3(8,4,1),256>>>(o1p, Wo, nullptr, part, 128,
                DIN, DIN, DIN, 0,0,0, 8, (long)NB*DIN);
        reduce_k<<<(NB*DIN)/1024,256>>>(part, o2p, bo, DIN, NB*DIN, 4, (long)NB*DIN);
        concat_k<<<(NB*(DIN+DM))/256,256>>>();
        // pre = cat @ Ws + bs : mma.sync bf16x3, 4 K-splits
        convA<<<(128*2560)/256,256>>>(catp, Abf, 2560, 2560);
        gemm_mma<<<dim3(32,4),256,MMA_SMEM>>>(Abf, BTpre, part, 2560, 120, 30, 4096);
        reduce_k<<<(NB*2*DM)/1024,256>>>(part, prep, bs, 2*DM, NB*2*DM, 4, (long)NB*2*DM);
        glu_ln<<<NB,256>>>(ln_s_g, ln_s_b);
        trace_act<<<dim3(NB,DM/256),256>>>(ln_n_g, ln_n_b, Wn, bn, temp, t);
        sync_k<<<NB,256>>>(dec_o, al_o, 0, t);
        // pred = s @ Wout + bout : mma.sync bf16x3, 4 K-splits
        convA<<<(128*2112)/256,256>>>(sp, Abf, NREP, 2112);
        gemm_mma<<<dim3(32,4),256,MMA_SMEM>>>(Abf, BTpred, part, 2112, 99, 25, 4096);
        reduce_k<<<(NB*2*NS)/1024,256>>>(part, predp, bout, 2*NS, NB*2*NS, 4, (long)NB*2*NS);
        finalize<<<NB,256>>>(out, t);
    }
}